// round 12
// baseline (speedup 1.0000x reference)
#include <cuda_runtime.h>
#include <math.h>

// ---------------- problem constants ----------------
#define CDIM 768
#define LNUM 6
#define HNUM 12
#define HD   64
#define TLEN 1024
#define BSZ  2
#define VDIM 50257
#define VPAD 50304               // 393 * 128, zero-padded
#define MROWS (BSZ * TLEN)       // 2048

// ---------------- scratch (no allocation allowed) ----------------
__device__ __align__(16) float g_x   [MROWS * CDIM];
__device__ __align__(16) float g_xn  [MROWS * CDIM];
__device__ __align__(16) float g_att [MROWS * CDIM];
__device__ __align__(16) float g_qkv [MROWS * 3 * CDIM];
__device__ __align__(16) float g_h   [MROWS * 4 * CDIM];
__device__ __align__(16) float g_embT[CDIM * VPAD];

// ---------------- embedding ----------------
__global__ void embed_kernel(const int* __restrict__ idx,
                             const float* __restrict__ emb,
                             const float* __restrict__ pos) {
    int n = blockIdx.x;
    int tok = idx[n];
    int t = n & (TLEN - 1);
    const float* e = emb + (size_t)tok * CDIM;
    const float* p = pos + (size_t)t * CDIM;
    float* xr = g_x + (size_t)n * CDIM;
    for (int c = threadIdx.x; c < CDIM; c += blockDim.x)
        xr[c] = e[c] + p[c];
}

// ---------------- transpose emb [V,C] -> embT [C, VPAD] (zero padded) ----------------
__global__ void transpose_kernel(const float* __restrict__ emb) {
    __shared__ float tile[32][33];
    int v0 = blockIdx.x * 32;
    int c0 = blockIdx.y * 32;
    for (int i = threadIdx.y; i < 32; i += 8) {
        int v = v0 + i;
        tile[i][threadIdx.x] = (v < VDIM) ? emb[(size_t)v * CDIM + c0 + threadIdx.x] : 0.f;
    }
    __syncthreads();
    for (int i = threadIdx.y; i < 32; i += 8) {
        g_embT[(size_t)(c0 + i) * VPAD + v0 + threadIdx.x] = tile[threadIdx.x][i];
    }
}

// ---------------- layernorm (one block per row, C=768) ----------------
__global__ void __launch_bounds__(256) ln_kernel(const float* __restrict__ x,
                                                 const float* __restrict__ w,
                                                 const float* __restrict__ bb,
                                                 float* __restrict__ y) {
    __shared__ float red[8];
    __shared__ float bc[2];
    int row = blockIdx.x, t = threadIdx.x;
    const float* xr = x + (size_t)row * CDIM;
    float v0 = xr[t], v1 = xr[t + 256], v2 = xr[t + 512];
    float s = v0 + v1 + v2;
    #pragma unroll
    for (int o = 16; o; o >>= 1) s += __shfl_xor_sync(0xffffffffu, s, o);
    if ((t & 31) == 0) red[t >> 5] = s;
    __syncthreads();
    if (t == 0) {
        float tt = 0.f;
        #pragma unroll
        for (int i = 0; i < 8; i++) tt += red[i];
        bc[0] = tt * (1.f / 768.f);
    }
    __syncthreads();
    float mu = bc[0];
    float d0 = v0 - mu, d1 = v1 - mu, d2 = v2 - mu;
    float q = d0 * d0 + d1 * d1 + d2 * d2;
    __syncthreads();   // red reuse
    #pragma unroll
    for (int o = 16; o; o >>= 1) q += __shfl_xor_sync(0xffffffffu, q, o);
    if ((t & 31) == 0) red[t >> 5] = q;
    __syncthreads();
    if (t == 0) {
        float tt = 0.f;
        #pragma unroll
        for (int i = 0; i < 8; i++) tt += red[i];
        bc[1] = rsqrtf(tt * (1.f / 768.f) + 1e-5f);
    }
    __syncthreads();
    float inv = bc[1];
    float* yr = y + (size_t)row * CDIM;
    yr[t]       = d0 * inv * w[t]       + bb[t];
    yr[t + 256] = d1 * inv * w[t + 256] + bb[t + 256];
    yr[t + 512] = d2 * inv * w[t + 512] + bb[t + 512];
}

// ---------------- SGEMM: C[M,N] = A[M,K] @ B[K,N]  (lda = K) ----------------
// EPI: 0 = none, 1 = +bias then GELU, 2 = +resid, 3 = +bias +resid
#define GBM 128
#define GBN 128
#define GBK 16

template<int EPI>
__global__ void __launch_bounds__(256) gemm_kernel(
    const float* __restrict__ A, const float* __restrict__ B, float* __restrict__ Cc,
    const float* __restrict__ bias, const float* __restrict__ resid,
    int N, int K, int ldb, int ldc)
{
    __shared__ float As[GBK][132];   // K-transposed A tile, padded stride
    __shared__ float Bs[GBK][GBN];

    int tid = threadIdx.x;
    int bn = blockIdx.x * GBN;
    int bm = blockIdx.y * GBM;
    int tx = tid & 15, ty = tid >> 4;

    int arow = tid >> 2;             // 0..63
    int acol = (tid & 3) << 2;       // 0,4,8,12
    int brow = tid >> 5;             // 0..7
    int bcol = (tid & 31) << 2;      // 0..124

    const float* Ap = A + (size_t)(bm + arow) * K + acol;
    const float* Bp = B + (size_t)brow * ldb + bn + bcol;

    float4 ra0 = *(const float4*)Ap;
    float4 ra1 = *(const float4*)(Ap + (size_t)64 * K);
    float4 rb0 = *(const float4*)Bp;
    float4 rb1 = *(const float4*)(Bp + (size_t)8 * ldb);

    float acc[8][8];
    #pragma unroll
    for (int i = 0; i < 8; i++)
        #pragma unroll
        for (int j = 0; j < 8; j++) acc[i][j] = 0.f;

    int nk = K / GBK;
    for (int kt = 0; kt < nk; kt++) {
        As[acol + 0][arow] = ra0.x; As[acol + 1][arow] = ra0.y;
        As[acol + 2][arow] = ra0.z; As[acol + 3][arow] = ra0.w;
        As[acol + 0][arow + 64] = ra1.x; As[acol + 1][arow + 64] = ra1.y;
        As[acol + 2][arow + 64] = ra1.z; As[acol + 3][arow + 64] = ra1.w;
        *(float4*)&Bs[brow][bcol]     = rb0;
        *(float4*)&Bs[brow + 8][bcol] = rb1;
        __syncthreads();

        if (kt + 1 < nk) {
            ra0 = *(const float4*)(Ap + (kt + 1) * GBK);
            ra1 = *(const float4*)(Ap + (size_t)64 * K + (kt + 1) * GBK);
            rb0 = *(const float4*)(Bp + (size_t)(kt + 1) * GBK * ldb);
            rb1 = *(const float4*)(Bp + (size_t)((kt + 1) * GBK + 8) * ldb);
        }

        #pragma unroll
        for (int k = 0; k < GBK; k++) {
            float4 a0 = *(const float4*)&As[k][ty * 8];
            float4 a1 = *(const float4*)&As[k][ty * 8 + 4];
            float4 b0 = *(const float4*)&Bs[k][tx * 8];
            float4 b1 = *(const float4*)&Bs[k][tx * 8 + 4];
            float av[8] = {a0.x, a0.y, a0.z, a0.w, a1.x, a1.y, a1.z, a1.w};
            float bv[8] = {b0.x, b0.y, b0.z, b0.w, b1.x, b1.y, b1.z, b1.w};
            #pragma unroll
            for (int i = 0; i < 8; i++)
                #pragma unroll
                for (int j = 0; j < 8; j++)
                    acc[i][j] = fmaf(av[i], bv[j], acc[i][j]);
        }
        __syncthreads();
    }

    float bvv[8];
    if (EPI == 1 || EPI == 3) {
        #pragma unroll
        for (int j = 0; j < 8; j++) {
            int n = bn + tx * 8 + j;
            bvv[j] = (n < N) ? bias[n] : 0.f;
        }
    }
    #pragma unroll
    for (int i = 0; i < 8; i++) {
        int mrow = bm + ty * 8 + i;
        float* crow = Cc + (size_t)mrow * ldc;
        const float* rrow = (EPI == 2 || EPI == 3) ? (resid + (size_t)mrow * ldc) : nullptr;
        #pragma unroll
        for (int j = 0; j < 8; j++) {
            int n = bn + tx * 8 + j;
            if (n >= N) continue;
            float v = acc[i][j];
            if (EPI == 1 || EPI == 3) v += bvv[j];
            if (EPI == 1) v = 0.5f * v * (1.f + erff(v * 0.70710678118654752f));
            if (EPI == 2 || EPI == 3) v += rrow[n];
            crow[n] = v;
        }
    }
}

// ---------------- fused causal flash attention ----------------
// Block = (q-tile of 64 rows, head h, batch b). 128 threads:
// ty = tid/8 in [0,16) -> 4 q-rows each; tx = tid%8 -> 8 cols each.
#define FA_SM_FLOATS (3 * 64 * 65 + 64 * 64)
#define FA_SM_BYTES  (FA_SM_FLOATS * 4)

__global__ void __launch_bounds__(128) flash_kernel(const float* __restrict__ qkv,
                                                    float* __restrict__ out) {
    extern __shared__ float sm[];
    float* Qt = sm;                  // [64 d][65] Q transposed, pre-scaled
    float* Kt = Qt + 64 * 65;        // [64 d][65] K transposed
    float* Ps = Kt + 64 * 65;        // [64 r][65] probabilities
    float* Vs = Ps + 64 * 65;        // [64 r][64 d]

    const int C3 = 3 * CDIM;
    int qt = blockIdx.x, h = blockIdx.y, b = blockIdx.z;
    int tid = threadIdx.x;
    int tx = tid & 7, ty = tid >> 3;

    const float* base = qkv + (size_t)b * TLEN * C3 + h * HD;

    // load Q tile (transposed, scaled by 1/sqrt(64))
    for (int i = tid; i < 64 * 16; i += 128) {
        int r = i >> 4;
        int d4 = (i & 15) * 4;
        float4 qv = *(const float4*)(base + (size_t)(qt * 64 + r) * C3 + d4);
        Qt[(d4 + 0) * 65 + r] = qv.x * 0.125f;
        Qt[(d4 + 1) * 65 + r] = qv.y * 0.125f;
        Qt[(d4 + 2) * 65 + r] = qv.z * 0.125f;
        Qt[(d4 + 3) * 65 + r] = qv.w * 0.125f;
    }

    float o[4][8];
    float m[4], lsum[4];
    #pragma unroll
    for (int i = 0; i < 4; i++) {
        m[i] = -1e30f; lsum[i] = 0.f;
        #pragma unroll
        for (int j = 0; j < 8; j++) o[i][j] = 0.f;
    }

    for (int kt = 0; kt <= qt; kt++) {
        __syncthreads();   // protect Kt/Vs/Ps from previous iteration
        for (int i = tid; i < 64 * 16; i += 128) {
            int r = i >> 4;
            int d4 = (i & 15) * 4;
            const float* krow = base + CDIM + (size_t)(kt * 64 + r) * C3;
            float4 kv = *(const float4*)(krow + d4);
            Kt[(d4 + 0) * 65 + r] = kv.x;
            Kt[(d4 + 1) * 65 + r] = kv.y;
            Kt[(d4 + 2) * 65 + r] = kv.z;
            Kt[(d4 + 3) * 65 + r] = kv.w;
            float4 vv = *(const float4*)(krow + CDIM + d4);
            *(float4*)(Vs + r * 64 + d4) = vv;
        }
        __syncthreads();

        // S = Q @ K^T (64x64, 4x8 per thread)
        float s[4][8];
        #pragma unroll
        for (int i = 0; i < 4; i++)
            #pragma unroll
            for (int j = 0; j < 8; j++) s[i][j] = 0.f;

        #pragma unroll 8
        for (int k = 0; k < 64; k++) {
            float qa[4], kb[8];
            #pragma unroll
            for (int i = 0; i < 4; i++) qa[i] = Qt[k * 65 + ty * 4 + i];
            #pragma unroll
            for (int j = 0; j < 8; j++) kb[j] = Kt[k * 65 + tx * 8 + j];
            #pragma unroll
            for (int i = 0; i < 4; i++)
                #pragma unroll
                for (int j = 0; j < 8; j++)
                    s[i][j] = fmaf(qa[i], kb[j], s[i][j]);
        }

        if (kt == qt) {  // causal mask on diagonal tile
            #pragma unroll
            for (int i = 0; i < 4; i++)
                #pragma unroll
                for (int j = 0; j < 8; j++)
                    if (tx * 8 + j > ty * 4 + i) s[i][j] = -1e30f;
        }

        // online softmax + write P to smem
        #pragma unroll
        for (int i = 0; i < 4; i++) {
            float mt = s[i][0];
            #pragma unroll
            for (int j = 1; j < 8; j++) mt = fmaxf(mt, s[i][j]);
            mt = fmaxf(mt, __shfl_xor_sync(0xffffffffu, mt, 1));
            mt = fmaxf(mt, __shfl_xor_sync(0xffffffffu, mt, 2));
            mt = fmaxf(mt, __shfl_xor_sync(0xffffffffu, mt, 4));
            float mn = fmaxf(m[i], mt);
            float alpha = __expf(m[i] - mn);
            m[i] = mn;
            float rs = 0.f;
            #pragma unroll
            for (int j = 0; j < 8; j++) {
                float p = __expf(s[i][j] - mn);
                s[i][j] = p;
                rs += p;
            }
            rs += __shfl_xor_sync(0xffffffffu, rs, 1);
            rs += __shfl_xor_sync(0xffffffffu, rs, 2);
            rs += __shfl_xor_sync(0xffffffffu, rs, 4);
            lsum[i] = lsum[i] * alpha + rs;
            #pragma unroll
            for (int j = 0; j < 8; j++) o[i][j] *= alpha;
            #pragma unroll
            for (int j = 0; j < 8; j++)
                Ps[(ty * 4 + i) * 65 + tx * 8 + j] = s[i][j];
        }
        __syncthreads();

        // O += P @ V
        #pragma unroll 4
        for (int kk = 0; kk < 64; kk++) {
            float pa[4];
            #pragma unroll
            for (int i = 0; i < 4; i++) pa[i] = Ps[(ty * 4 + i) * 65 + kk];
            float4 v0 = *(const float4*)(Vs + kk * 64 + tx * 8);
            float4 v1 = *(const float4*)(Vs + kk * 64 + tx * 8 + 4);
            #pragma unroll
            for (int i = 0; i < 4; i++) {
                o[i][0] = fmaf(pa[i], v0.x, o[i][0]);
                o[i][1] = fmaf(pa[i], v0.y, o[i][1]);
                o[i][2] = fmaf(pa[i], v0.z, o[i][2]);
                o[i][3] = fmaf(pa[i], v0.w, o[i][3]);
                o[i][4] = fmaf(pa[i], v1.x, o[i][4]);
                o[i][5] = fmaf(pa[i], v1.y, o[i][5]);
                o[i][6] = fmaf(pa[i], v1.z, o[i][6]);
                o[i][7] = fmaf(pa[i], v1.w, o[i][7]);
            }
        }
    }

    // write out[(b,t), h*64 + d]
    #pragma unroll
    for (int i = 0; i < 4; i++) {
        float inv = 1.f / lsum[i];
        int r = qt * 64 + ty * 4 + i;
        float* orow = out + ((size_t)(b * TLEN + r)) * CDIM + h * HD + tx * 8;
        float4 w0 = make_float4(o[i][0] * inv, o[i][1] * inv, o[i][2] * inv, o[i][3] * inv);
        float4 w1 = make_float4(o[i][4] * inv, o[i][5] * inv, o[i][6] * inv, o[i][7] * inv);
        *(float4*)(orow)     = w0;
        *(float4*)(orow + 4) = w1;
    }
}

// ---------------- launch ----------------
extern "C" void kernel_launch(void* const* d_in, const int* in_sizes, int n_in,
                              void* d_out, int out_size) {
    (void)in_sizes; (void)n_in; (void)out_size;
    const int*   idx   = (const int*)d_in[0];
    const float* emb   = (const float*)d_in[1];
    const float* pos   = (const float*)d_in[2];
    const float* Wqkv  = (const float*)d_in[3];
    const float* Wproj = (const float*)d_in[4];
    const float* ln1w  = (const float*)d_in[5];
    const float* ln1b  = (const float*)d_in[6];
    const float* ln2w  = (const float*)d_in[7];
    const float* ln2b  = (const float*)d_in[8];
    const float* W1    = (const float*)d_in[9];
    const float* b1    = (const float*)d_in[10];
    const float* W2    = (const float*)d_in[11];
    const float* b2    = (const float*)d_in[12];
    const float* lnfw  = (const float*)d_in[13];
    const float* lnfb  = (const float*)d_in[14];
    float* out = (float*)d_out;

    float *x, *xn, *att, *qkv, *hbuf, *embT;
    cudaGetSymbolAddress((void**)&x,    g_x);
    cudaGetSymbolAddress((void**)&xn,   g_xn);
    cudaGetSymbolAddress((void**)&att,  g_att);
    cudaGetSymbolAddress((void**)&qkv,  g_qkv);
    cudaGetSymbolAddress((void**)&hbuf, g_h);
    cudaGetSymbolAddress((void**)&embT, g_embT);

    cudaFuncSetAttribute(flash_kernel, cudaFuncAttributeMaxDynamicSharedMemorySize, FA_SM_BYTES);

    transpose_kernel<<<dim3(VPAD / 32, CDIM / 32), dim3(32, 8)>>>(emb);
    embed_kernel<<<MROWS, 256>>>(idx, emb, pos);

    const dim3 blk(256);
    for (int l = 0; l < LNUM; l++) {
        ln_kernel<<<MROWS, blk>>>(x, ln1w + l * CDIM, ln1b + l * CDIM, xn);

        gemm_kernel<0><<<dim3(3 * CDIM / GBN, MROWS / GBM), blk>>>(
            xn, Wqkv + (size_t)l * CDIM * 3 * CDIM, qkv,
            nullptr, nullptr, 3 * CDIM, CDIM, 3 * CDIM, 3 * CDIM);

        flash_kernel<<<dim3(TLEN / 64, HNUM, BSZ), 128, FA_SM_BYTES>>>(qkv, att);

        gemm_kernel<2><<<dim3(CDIM / GBN, MROWS / GBM), blk>>>(
            att, Wproj + (size_t)l * CDIM * CDIM, x,
            nullptr, x, CDIM, CDIM, CDIM, CDIM);

        ln_kernel<<<MROWS, blk>>>(x, ln2w + l * CDIM, ln2b + l * CDIM, xn);

        gemm_kernel<1><<<dim3(4 * CDIM / GBN, MROWS / GBM), blk>>>(
            xn, W1 + (size_t)l * CDIM * 4 * CDIM, hbuf,
            b1 + (size_t)l * 4 * CDIM, nullptr, 4 * CDIM, CDIM, 4 * CDIM, 4 * CDIM);

        gemm_kernel<3><<<dim3(CDIM / GBN, MROWS / GBM), blk>>>(
            hbuf, W2 + (size_t)l * 4 * CDIM * CDIM, x,
            b2 + (size_t)l * CDIM, x, CDIM, 4 * CDIM, CDIM, CDIM);
    }

    ln_kernel<<<MROWS, blk>>>(x, lnfw, lnfb, xn);

    // tied head: xn [2048,768] @ embT [768, VPAD] -> out [2048, 50257]
    gemm_kernel<0><<<dim3(VPAD / GBN, MROWS / GBM), blk>>>(
        xn, embT, out, nullptr, nullptr, VDIM, CDIM, VPAD, VDIM);
}

// round 13
// speedup vs baseline: 1.0006x; 1.0006x over previous
#include <cuda_runtime.h>
#include <math.h>

// ---------------- problem constants ----------------
#define CDIM 768
#define LNUM 6
#define HNUM 12
#define HD   64
#define TLEN 1024
#define BSZ  2
#define VDIM 50257
#define VPAD 50304               // 393 * 128, zero-padded
#define MROWS (BSZ * TLEN)       // 2048

// ---------------- scratch (no allocation allowed) ----------------
__device__ __align__(16) float g_x   [MROWS * CDIM];
__device__ __align__(16) float g_xn  [MROWS * CDIM];
__device__ __align__(16) float g_att [MROWS * CDIM];
__device__ __align__(16) float g_qkv [MROWS * 3 * CDIM];
__device__ __align__(16) float g_h   [MROWS * 4 * CDIM];
__device__ __align__(16) float g_embT[CDIM * VPAD];

// ---------------- embedding ----------------
__global__ void embed_kernel(const int* __restrict__ idx,
                             const float* __restrict__ emb,
                             const float* __restrict__ pos) {
    int n = blockIdx.x;
    int tok = idx[n];
    int t = n & (TLEN - 1);
    const float* e = emb + (size_t)tok * CDIM;
    const float* p = pos + (size_t)t * CDIM;
    float* xr = g_x + (size_t)n * CDIM;
    for (int c = threadIdx.x; c < CDIM; c += blockDim.x)
        xr[c] = e[c] + p[c];
}

// ---------------- transpose emb [V,C] -> embT [C, VPAD] (zero padded) ----------------
__global__ void transpose_kernel(const float* __restrict__ emb) {
    __shared__ float tile[32][33];
    int v0 = blockIdx.x * 32;
    int c0 = blockIdx.y * 32;
    for (int i = threadIdx.y; i < 32; i += 8) {
        int v = v0 + i;
        tile[i][threadIdx.x] = (v < VDIM) ? emb[(size_t)v * CDIM + c0 + threadIdx.x] : 0.f;
    }
    __syncthreads();
    for (int i = threadIdx.y; i < 32; i += 8) {
        g_embT[(size_t)(c0 + i) * VPAD + v0 + threadIdx.x] = tile[threadIdx.x][i];
    }
}

// ---------------- layernorm (one block per row, C=768) ----------------
__global__ void __launch_bounds__(256) ln_kernel(const float* __restrict__ x,
                                                 const float* __restrict__ w,
                                                 const float* __restrict__ bb,
                                                 float* __restrict__ y) {
    __shared__ float red[8];
    __shared__ float bc[2];
    int row = blockIdx.x, t = threadIdx.x;
    const float* xr = x + (size_t)row * CDIM;
    float v0 = xr[t], v1 = xr[t + 256], v2 = xr[t + 512];
    float s = v0 + v1 + v2;
    #pragma unroll
    for (int o = 16; o; o >>= 1) s += __shfl_xor_sync(0xffffffffu, s, o);
    if ((t & 31) == 0) red[t >> 5] = s;
    __syncthreads();
    if (t == 0) {
        float tt = 0.f;
        #pragma unroll
        for (int i = 0; i < 8; i++) tt += red[i];
        bc[0] = tt * (1.f / 768.f);
    }
    __syncthreads();
    float mu = bc[0];
    float d0 = v0 - mu, d1 = v1 - mu, d2 = v2 - mu;
    float q = d0 * d0 + d1 * d1 + d2 * d2;
    __syncthreads();   // red reuse
    #pragma unroll
    for (int o = 16; o; o >>= 1) q += __shfl_xor_sync(0xffffffffu, q, o);
    if ((t & 31) == 0) red[t >> 5] = q;
    __syncthreads();
    if (t == 0) {
        float tt = 0.f;
        #pragma unroll
        for (int i = 0; i < 8; i++) tt += red[i];
        bc[1] = rsqrtf(tt * (1.f / 768.f) + 1e-5f);
    }
    __syncthreads();
    float inv = bc[1];
    float* yr = y + (size_t)row * CDIM;
    yr[t]       = d0 * inv * w[t]       + bb[t];
    yr[t + 256] = d1 * inv * w[t + 256] + bb[t + 256];
    yr[t + 512] = d2 * inv * w[t + 512] + bb[t + 512];
}

// ---------------- SGEMM: C[M,N] = A[M,K] @ B[K,N]  (lda = K) ----------------
// EPI: 0 = none, 1 = +bias then GELU, 2 = +resid, 3 = +bias +resid
#define GBM 128
#define GBN 128
#define GBK 16

template<int EPI>
__global__ void __launch_bounds__(256) gemm_kernel(
    const float* __restrict__ A, const float* __restrict__ B, float* __restrict__ Cc,
    const float* __restrict__ bias, const float* __restrict__ resid,
    int N, int K, int ldb, int ldc)
{
    __shared__ float As[GBK][132];   // K-transposed A tile, padded stride
    __shared__ float Bs[GBK][GBN];

    int tid = threadIdx.x;
    int bn = blockIdx.x * GBN;
    int bm = blockIdx.y * GBM;
    int tx = tid & 15, ty = tid >> 4;

    int arow = tid >> 2;             // 0..63
    int acol = (tid & 3) << 2;       // 0,4,8,12
    int brow = tid >> 5;             // 0..7
    int bcol = (tid & 31) << 2;      // 0..124

    const float* Ap = A + (size_t)(bm + arow) * K + acol;
    const float* Bp = B + (size_t)brow * ldb + bn + bcol;

    float4 ra0 = *(const float4*)Ap;
    float4 ra1 = *(const float4*)(Ap + (size_t)64 * K);
    float4 rb0 = *(const float4*)Bp;
    float4 rb1 = *(const float4*)(Bp + (size_t)8 * ldb);

    float acc[8][8];
    #pragma unroll
    for (int i = 0; i < 8; i++)
        #pragma unroll
        for (int j = 0; j < 8; j++) acc[i][j] = 0.f;

    int nk = K / GBK;
    for (int kt = 0; kt < nk; kt++) {
        As[acol + 0][arow] = ra0.x; As[acol + 1][arow] = ra0.y;
        As[acol + 2][arow] = ra0.z; As[acol + 3][arow] = ra0.w;
        As[acol + 0][arow + 64] = ra1.x; As[acol + 1][arow + 64] = ra1.y;
        As[acol + 2][arow + 64] = ra1.z; As[acol + 3][arow + 64] = ra1.w;
        *(float4*)&Bs[brow][bcol]     = rb0;
        *(float4*)&Bs[brow + 8][bcol] = rb1;
        __syncthreads();

        if (kt + 1 < nk) {
            ra0 = *(const float4*)(Ap + (kt + 1) * GBK);
            ra1 = *(const float4*)(Ap + (size_t)64 * K + (kt + 1) * GBK);
            rb0 = *(const float4*)(Bp + (size_t)(kt + 1) * GBK * ldb);
            rb1 = *(const float4*)(Bp + (size_t)((kt + 1) * GBK + 8) * ldb);
        }

        #pragma unroll
        for (int k = 0; k < GBK; k++) {
            float4 a0 = *(const float4*)&As[k][ty * 8];
            float4 a1 = *(const float4*)&As[k][ty * 8 + 4];
            float4 b0 = *(const float4*)&Bs[k][tx * 8];
            float4 b1 = *(const float4*)&Bs[k][tx * 8 + 4];
            float av[8] = {a0.x, a0.y, a0.z, a0.w, a1.x, a1.y, a1.z, a1.w};
            float bv[8] = {b0.x, b0.y, b0.z, b0.w, b1.x, b1.y, b1.z, b1.w};
            #pragma unroll
            for (int i = 0; i < 8; i++)
                #pragma unroll
                for (int j = 0; j < 8; j++)
                    acc[i][j] = fmaf(av[i], bv[j], acc[i][j]);
        }
        __syncthreads();
    }

    float bvv[8];
    if (EPI == 1 || EPI == 3) {
        #pragma unroll
        for (int j = 0; j < 8; j++) {
            int n = bn + tx * 8 + j;
            bvv[j] = (n < N) ? bias[n] : 0.f;
        }
    }
    #pragma unroll
    for (int i = 0; i < 8; i++) {
        int mrow = bm + ty * 8 + i;
        float* crow = Cc + (size_t)mrow * ldc;
        const float* rrow = (EPI == 2 || EPI == 3) ? (resid + (size_t)mrow * ldc) : nullptr;
        #pragma unroll
        for (int j = 0; j < 8; j++) {
            int n = bn + tx * 8 + j;
            if (n >= N) continue;
            float v = acc[i][j];
            if (EPI == 1 || EPI == 3) v += bvv[j];
            if (EPI == 1) v = 0.5f * v * (1.f + erff(v * 0.70710678118654752f));
            if (EPI == 2 || EPI == 3) v += rrow[n];
            crow[n] = v;
        }
    }
}

// ---------------- fused causal flash attention ----------------
// Block = (q-tile of 64 rows, head h, batch b). 128 threads:
// ty = tid/8 in [0,16) -> 4 q-rows each; tx = tid%8 -> 8 cols each.
#define FA_SM_FLOATS (3 * 64 * 65 + 64 * 64)
#define FA_SM_BYTES  (FA_SM_FLOATS * 4)

__global__ void __launch_bounds__(128) flash_kernel(const float* __restrict__ qkv,
                                                    float* __restrict__ out) {
    extern __shared__ float sm[];
    float* Qt = sm;                  // [64 d][65] Q transposed, pre-scaled
    float* Kt = Qt + 64 * 65;        // [64 d][65] K transposed
    float* Ps = Kt + 64 * 65;        // [64 r][65] probabilities
    float* Vs = Ps + 64 * 65;        // [64 r][64 d]

    const int C3 = 3 * CDIM;
    int qt = blockIdx.x, h = blockIdx.y, b = blockIdx.z;
    int tid = threadIdx.x;
    int tx = tid & 7, ty = tid >> 3;

    const float* base = qkv + (size_t)b * TLEN * C3 + h * HD;

    // load Q tile (transposed, scaled by 1/sqrt(64))
    for (int i = tid; i < 64 * 16; i += 128) {
        int r = i >> 4;
        int d4 = (i & 15) * 4;
        float4 qv = *(const float4*)(base + (size_t)(qt * 64 + r) * C3 + d4);
        Qt[(d4 + 0) * 65 + r] = qv.x * 0.125f;
        Qt[(d4 + 1) * 65 + r] = qv.y * 0.125f;
        Qt[(d4 + 2) * 65 + r] = qv.z * 0.125f;
        Qt[(d4 + 3) * 65 + r] = qv.w * 0.125f;
    }

    float o[4][8];
    float m[4], lsum[4];
    #pragma unroll
    for (int i = 0; i < 4; i++) {
        m[i] = -1e30f; lsum[i] = 0.f;
        #pragma unroll
        for (int j = 0; j < 8; j++) o[i][j] = 0.f;
    }

    for (int kt = 0; kt <= qt; kt++) {
        __syncthreads();   // protect Kt/Vs/Ps from previous iteration
        for (int i = tid; i < 64 * 16; i += 128) {
            int r = i >> 4;
            int d4 = (i & 15) * 4;
            const float* krow = base + CDIM + (size_t)(kt * 64 + r) * C3;
            float4 kv = *(const float4*)(krow + d4);
            Kt[(d4 + 0) * 65 + r] = kv.x;
            Kt[(d4 + 1) * 65 + r] = kv.y;
            Kt[(d4 + 2) * 65 + r] = kv.z;
            Kt[(d4 + 3) * 65 + r] = kv.w;
            float4 vv = *(const float4*)(krow + CDIM + d4);
            *(float4*)(Vs + r * 64 + d4) = vv;
        }
        __syncthreads();

        // S = Q @ K^T (64x64, 4x8 per thread)
        float s[4][8];
        #pragma unroll
        for (int i = 0; i < 4; i++)
            #pragma unroll
            for (int j = 0; j < 8; j++) s[i][j] = 0.f;

        #pragma unroll 8
        for (int k = 0; k < 64; k++) {
            float qa[4], kb[8];
            #pragma unroll
            for (int i = 0; i < 4; i++) qa[i] = Qt[k * 65 + ty * 4 + i];
            #pragma unroll
            for (int j = 0; j < 8; j++) kb[j] = Kt[k * 65 + tx * 8 + j];
            #pragma unroll
            for (int i = 0; i < 4; i++)
                #pragma unroll
                for (int j = 0; j < 8; j++)
                    s[i][j] = fmaf(qa[i], kb[j], s[i][j]);
        }

        if (kt == qt) {  // causal mask on diagonal tile
            #pragma unroll
            for (int i = 0; i < 4; i++)
                #pragma unroll
                for (int j = 0; j < 8; j++)
                    if (tx * 8 + j > ty * 4 + i) s[i][j] = -1e30f;
        }

        // online softmax + write P to smem
        #pragma unroll
        for (int i = 0; i < 4; i++) {
            float mt = s[i][0];
            #pragma unroll
            for (int j = 1; j < 8; j++) mt = fmaxf(mt, s[i][j]);
            mt = fmaxf(mt, __shfl_xor_sync(0xffffffffu, mt, 1));
            mt = fmaxf(mt, __shfl_xor_sync(0xffffffffu, mt, 2));
            mt = fmaxf(mt, __shfl_xor_sync(0xffffffffu, mt, 4));
            float mn = fmaxf(m[i], mt);
            float alpha = __expf(m[i] - mn);
            m[i] = mn;
            float rs = 0.f;
            #pragma unroll
            for (int j = 0; j < 8; j++) {
                float p = __expf(s[i][j] - mn);
                s[i][j] = p;
                rs += p;
            }
            rs += __shfl_xor_sync(0xffffffffu, rs, 1);
            rs += __shfl_xor_sync(0xffffffffu, rs, 2);
            rs += __shfl_xor_sync(0xffffffffu, rs, 4);
            lsum[i] = lsum[i] * alpha + rs;
            #pragma unroll
            for (int j = 0; j < 8; j++) o[i][j] *= alpha;
            #pragma unroll
            for (int j = 0; j < 8; j++)
                Ps[(ty * 4 + i) * 65 + tx * 8 + j] = s[i][j];
        }
        __syncthreads();

        // O += P @ V
        #pragma unroll 4
        for (int kk = 0; kk < 64; kk++) {
            float pa[4];
            #pragma unroll
            for (int i = 0; i < 4; i++) pa[i] = Ps[(ty * 4 + i) * 65 + kk];
            float4 v0 = *(const float4*)(Vs + kk * 64 + tx * 8);
            float4 v1 = *(const float4*)(Vs + kk * 64 + tx * 8 + 4);
            #pragma unroll
            for (int i = 0; i < 4; i++) {
                o[i][0] = fmaf(pa[i], v0.x, o[i][0]);
                o[i][1] = fmaf(pa[i], v0.y, o[i][1]);
                o[i][2] = fmaf(pa[i], v0.z, o[i][2]);
                o[i][3] = fmaf(pa[i], v0.w, o[i][3]);
                o[i][4] = fmaf(pa[i], v1.x, o[i][4]);
                o[i][5] = fmaf(pa[i], v1.y, o[i][5]);
                o[i][6] = fmaf(pa[i], v1.z, o[i][6]);
                o[i][7] = fmaf(pa[i], v1.w, o[i][7]);
            }
        }
    }

    // write out[(b,t), h*64 + d]
    #pragma unroll
    for (int i = 0; i < 4; i++) {
        float inv = 1.f / lsum[i];
        int r = qt * 64 + ty * 4 + i;
        float* orow = out + ((size_t)(b * TLEN + r)) * CDIM + h * HD + tx * 8;
        float4 w0 = make_float4(o[i][0] * inv, o[i][1] * inv, o[i][2] * inv, o[i][3] * inv);
        float4 w1 = make_float4(o[i][4] * inv, o[i][5] * inv, o[i][6] * inv, o[i][7] * inv);
        *(float4*)(orow)     = w0;
        *(float4*)(orow + 4) = w1;
    }
}

// ---------------- launch ----------------
extern "C" void kernel_launch(void* const* d_in, const int* in_sizes, int n_in,
                              void* d_out, int out_size) {
    (void)in_sizes; (void)n_in; (void)out_size;
    const int*   idx   = (const int*)d_in[0];
    const float* emb   = (const float*)d_in[1];
    const float* pos   = (const float*)d_in[2];
    const float* Wqkv  = (const float*)d_in[3];
    const float* Wproj = (const float*)d_in[4];
    const float* ln1w  = (const float*)d_in[5];
    const float* ln1b  = (const float*)d_in[6];
    const float* ln2w  = (const float*)d_in[7];
    const float* ln2b  = (const float*)d_in[8];
    const float* W1    = (const float*)d_in[9];
    const float* b1    = (const float*)d_in[10];
    const float* W2    = (const float*)d_in[11];
    const float* b2    = (const float*)d_in[12];
    const float* lnfw  = (const float*)d_in[13];
    const float* lnfb  = (const float*)d_in[14];
    float* out = (float*)d_out;

    float *x, *xn, *att, *qkv, *hbuf, *embT;
    cudaGetSymbolAddress((void**)&x,    g_x);
    cudaGetSymbolAddress((void**)&xn,   g_xn);
    cudaGetSymbolAddress((void**)&att,  g_att);
    cudaGetSymbolAddress((void**)&qkv,  g_qkv);
    cudaGetSymbolAddress((void**)&hbuf, g_h);
    cudaGetSymbolAddress((void**)&embT, g_embT);

    cudaFuncSetAttribute(flash_kernel, cudaFuncAttributeMaxDynamicSharedMemorySize, FA_SM_BYTES);

    transpose_kernel<<<dim3(VPAD / 32, CDIM / 32), dim3(32, 8)>>>(emb);
    embed_kernel<<<MROWS, 256>>>(idx, emb, pos);

    const dim3 blk(256);
    for (int l = 0; l < LNUM; l++) {
        ln_kernel<<<MROWS, blk>>>(x, ln1w + l * CDIM, ln1b + l * CDIM, xn);

        gemm_kernel<0><<<dim3(3 * CDIM / GBN, MROWS / GBM), blk>>>(
            xn, Wqkv + (size_t)l * CDIM * 3 * CDIM, qkv,
            nullptr, nullptr, 3 * CDIM, CDIM, 3 * CDIM, 3 * CDIM);

        flash_kernel<<<dim3(TLEN / 64, HNUM, BSZ), 128, FA_SM_BYTES>>>(qkv, att);

        gemm_kernel<2><<<dim3(CDIM / GBN, MROWS / GBM), blk>>>(
            att, Wproj + (size_t)l * CDIM * CDIM, x,
            nullptr, x, CDIM, CDIM, CDIM, CDIM);

        ln_kernel<<<MROWS, blk>>>(x, ln2w + l * CDIM, ln2b + l * CDIM, xn);

        gemm_kernel<1><<<dim3(4 * CDIM / GBN, MROWS / GBM), blk>>>(
            xn, W1 + (size_t)l * CDIM * 4 * CDIM, hbuf,
            b1 + (size_t)l * 4 * CDIM, nullptr, 4 * CDIM, CDIM, 4 * CDIM, 4 * CDIM);

        gemm_kernel<3><<<dim3(CDIM / GBN, MROWS / GBM), blk>>>(
            hbuf, W2 + (size_t)l * 4 * CDIM * CDIM, x,
            b2 + (size_t)l * CDIM, x, CDIM, 4 * CDIM, CDIM, CDIM);
    }

    ln_kernel<<<MROWS, blk>>>(x, lnfw, lnfb, xn);

    // tied head: xn [2048,768] @ embT [768, VPAD] -> out [2048, 50257]
    gemm_kernel<0><<<dim3(VPAD / GBN, MROWS / GBM), blk>>>(
        xn, embT, out, nullptr, nullptr, VDIM, CDIM, VPAD, VDIM);
}

// round 14
// speedup vs baseline: 1.0006x; 1.0001x over previous
#include <cuda_runtime.h>
#include <math.h>

// ---------------- problem constants ----------------
#define CDIM 768
#define LNUM 6
#define HNUM 12
#define HD   64
#define TLEN 1024
#define BSZ  2
#define VDIM 50257
#define VPAD 50304               // 393 * 128, zero-padded
#define MROWS (BSZ * TLEN)       // 2048

// ---------------- scratch (no allocation allowed) ----------------
__device__ __align__(16) float g_x   [MROWS * CDIM];
__device__ __align__(16) float g_xn  [MROWS * CDIM];
__device__ __align__(16) float g_att [MROWS * CDIM];
__device__ __align__(16) float g_qkv [MROWS * 3 * CDIM];
__device__ __align__(16) float g_h   [MROWS * 4 * CDIM];
__device__ __align__(16) float g_embT[CDIM * VPAD];

// ---------------- embedding ----------------
__global__ void embed_kernel(const int* __restrict__ idx,
                             const float* __restrict__ emb,
                             const float* __restrict__ pos) {
    int n = blockIdx.x;
    int tok = idx[n];
    int t = n & (TLEN - 1);
    const float* e = emb + (size_t)tok * CDIM;
    const float* p = pos + (size_t)t * CDIM;
    float* xr = g_x + (size_t)n * CDIM;
    for (int c = threadIdx.x; c < CDIM; c += blockDim.x)
        xr[c] = e[c] + p[c];
}

// ---------------- transpose emb [V,C] -> embT [C, VPAD] (zero padded) ----------------
__global__ void transpose_kernel(const float* __restrict__ emb) {
    __shared__ float tile[32][33];
    int v0 = blockIdx.x * 32;
    int c0 = blockIdx.y * 32;
    for (int i = threadIdx.y; i < 32; i += 8) {
        int v = v0 + i;
        tile[i][threadIdx.x] = (v < VDIM) ? emb[(size_t)v * CDIM + c0 + threadIdx.x] : 0.f;
    }
    __syncthreads();
    for (int i = threadIdx.y; i < 32; i += 8) {
        g_embT[(size_t)(c0 + i) * VPAD + v0 + threadIdx.x] = tile[threadIdx.x][i];
    }
}

// ---------------- layernorm (one block per row, C=768) ----------------
__global__ void __launch_bounds__(256) ln_kernel(const float* __restrict__ x,
                                                 const float* __restrict__ w,
                                                 const float* __restrict__ bb,
                                                 float* __restrict__ y) {
    __shared__ float red[8];
    __shared__ float bc[2];
    int row = blockIdx.x, t = threadIdx.x;
    const float* xr = x + (size_t)row * CDIM;
    float v0 = xr[t], v1 = xr[t + 256], v2 = xr[t + 512];
    float s = v0 + v1 + v2;
    #pragma unroll
    for (int o = 16; o; o >>= 1) s += __shfl_xor_sync(0xffffffffu, s, o);
    if ((t & 31) == 0) red[t >> 5] = s;
    __syncthreads();
    if (t == 0) {
        float tt = 0.f;
        #pragma unroll
        for (int i = 0; i < 8; i++) tt += red[i];
        bc[0] = tt * (1.f / 768.f);
    }
    __syncthreads();
    float mu = bc[0];
    float d0 = v0 - mu, d1 = v1 - mu, d2 = v2 - mu;
    float q = d0 * d0 + d1 * d1 + d2 * d2;
    __syncthreads();   // red reuse
    #pragma unroll
    for (int o = 16; o; o >>= 1) q += __shfl_xor_sync(0xffffffffu, q, o);
    if ((t & 31) == 0) red[t >> 5] = q;
    __syncthreads();
    if (t == 0) {
        float tt = 0.f;
        #pragma unroll
        for (int i = 0; i < 8; i++) tt += red[i];
        bc[1] = rsqrtf(tt * (1.f / 768.f) + 1e-5f);
    }
    __syncthreads();
    float inv = bc[1];
    float* yr = y + (size_t)row * CDIM;
    yr[t]       = d0 * inv * w[t]       + bb[t];
    yr[t + 256] = d1 * inv * w[t + 256] + bb[t + 256];
    yr[t + 512] = d2 * inv * w[t + 512] + bb[t + 512];
}

// ---------------- SGEMM: C[M,N] = A[M,K] @ B[K,N]  (lda = K) ----------------
// EPI: 0 = none, 1 = +bias then GELU, 2 = +resid, 3 = +bias +resid
#define GBM 128
#define GBN 128
#define GBK 16

template<int EPI>
__global__ void __launch_bounds__(256) gemm_kernel(
    const float* __restrict__ A, const float* __restrict__ B, float* __restrict__ Cc,
    const float* __restrict__ bias, const float* __restrict__ resid,
    int N, int K, int ldb, int ldc)
{
    __shared__ float As[GBK][132];   // K-transposed A tile, padded stride
    __shared__ float Bs[GBK][GBN];

    int tid = threadIdx.x;
    int bn = blockIdx.x * GBN;
    int bm = blockIdx.y * GBM;
    int tx = tid & 15, ty = tid >> 4;

    int arow = tid >> 2;             // 0..63
    int acol = (tid & 3) << 2;       // 0,4,8,12
    int brow = tid >> 5;             // 0..7
    int bcol = (tid & 31) << 2;      // 0..124

    const float* Ap = A + (size_t)(bm + arow) * K + acol;
    const float* Bp = B + (size_t)brow * ldb + bn + bcol;

    float4 ra0 = *(const float4*)Ap;
    float4 ra1 = *(const float4*)(Ap + (size_t)64 * K);
    float4 rb0 = *(const float4*)Bp;
    float4 rb1 = *(const float4*)(Bp + (size_t)8 * ldb);

    float acc[8][8];
    #pragma unroll
    for (int i = 0; i < 8; i++)
        #pragma unroll
        for (int j = 0; j < 8; j++) acc[i][j] = 0.f;

    int nk = K / GBK;
    for (int kt = 0; kt < nk; kt++) {
        As[acol + 0][arow] = ra0.x; As[acol + 1][arow] = ra0.y;
        As[acol + 2][arow] = ra0.z; As[acol + 3][arow] = ra0.w;
        As[acol + 0][arow + 64] = ra1.x; As[acol + 1][arow + 64] = ra1.y;
        As[acol + 2][arow + 64] = ra1.z; As[acol + 3][arow + 64] = ra1.w;
        *(float4*)&Bs[brow][bcol]     = rb0;
        *(float4*)&Bs[brow + 8][bcol] = rb1;
        __syncthreads();

        if (kt + 1 < nk) {
            ra0 = *(const float4*)(Ap + (kt + 1) * GBK);
            ra1 = *(const float4*)(Ap + (size_t)64 * K + (kt + 1) * GBK);
            rb0 = *(const float4*)(Bp + (size_t)(kt + 1) * GBK * ldb);
            rb1 = *(const float4*)(Bp + (size_t)((kt + 1) * GBK + 8) * ldb);
        }

        #pragma unroll
        for (int k = 0; k < GBK; k++) {
            float4 a0 = *(const float4*)&As[k][ty * 8];
            float4 a1 = *(const float4*)&As[k][ty * 8 + 4];
            float4 b0 = *(const float4*)&Bs[k][tx * 8];
            float4 b1 = *(const float4*)&Bs[k][tx * 8 + 4];
            float av[8] = {a0.x, a0.y, a0.z, a0.w, a1.x, a1.y, a1.z, a1.w};
            float bv[8] = {b0.x, b0.y, b0.z, b0.w, b1.x, b1.y, b1.z, b1.w};
            #pragma unroll
            for (int i = 0; i < 8; i++)
                #pragma unroll
                for (int j = 0; j < 8; j++)
                    acc[i][j] = fmaf(av[i], bv[j], acc[i][j]);
        }
        __syncthreads();
    }

    float bvv[8];
    if (EPI == 1 || EPI == 3) {
        #pragma unroll
        for (int j = 0; j < 8; j++) {
            int n = bn + tx * 8 + j;
            bvv[j] = (n < N) ? bias[n] : 0.f;
        }
    }
    #pragma unroll
    for (int i = 0; i < 8; i++) {
        int mrow = bm + ty * 8 + i;
        float* crow = Cc + (size_t)mrow * ldc;
        const float* rrow = (EPI == 2 || EPI == 3) ? (resid + (size_t)mrow * ldc) : nullptr;
        #pragma unroll
        for (int j = 0; j < 8; j++) {
            int n = bn + tx * 8 + j;
            if (n >= N) continue;
            float v = acc[i][j];
            if (EPI == 1 || EPI == 3) v += bvv[j];
            if (EPI == 1) v = 0.5f * v * (1.f + erff(v * 0.70710678118654752f));
            if (EPI == 2 || EPI == 3) v += rrow[n];
            crow[n] = v;
        }
    }
}

// ---------------- fused causal flash attention ----------------
// Block = (q-tile of 64 rows, head h, batch b). 128 threads:
// ty = tid/8 in [0,16) -> 4 q-rows each; tx = tid%8 -> 8 cols each.
#define FA_SM_FLOATS (3 * 64 * 65 + 64 * 64)
#define FA_SM_BYTES  (FA_SM_FLOATS * 4)

__global__ void __launch_bounds__(128) flash_kernel(const float* __restrict__ qkv,
                                                    float* __restrict__ out) {
    extern __shared__ float sm[];
    float* Qt = sm;                  // [64 d][65] Q transposed, pre-scaled
    float* Kt = Qt + 64 * 65;        // [64 d][65] K transposed
    float* Ps = Kt + 64 * 65;        // [64 r][65] probabilities
    float* Vs = Ps + 64 * 65;        // [64 r][64 d]

    const int C3 = 3 * CDIM;
    int qt = blockIdx.x, h = blockIdx.y, b = blockIdx.z;
    int tid = threadIdx.x;
    int tx = tid & 7, ty = tid >> 3;

    const float* base = qkv + (size_t)b * TLEN * C3 + h * HD;

    // load Q tile (transposed, scaled by 1/sqrt(64))
    for (int i = tid; i < 64 * 16; i += 128) {
        int r = i >> 4;
        int d4 = (i & 15) * 4;
        float4 qv = *(const float4*)(base + (size_t)(qt * 64 + r) * C3 + d4);
        Qt[(d4 + 0) * 65 + r] = qv.x * 0.125f;
        Qt[(d4 + 1) * 65 + r] = qv.y * 0.125f;
        Qt[(d4 + 2) * 65 + r] = qv.z * 0.125f;
        Qt[(d4 + 3) * 65 + r] = qv.w * 0.125f;
    }

    float o[4][8];
    float m[4], lsum[4];
    #pragma unroll
    for (int i = 0; i < 4; i++) {
        m[i] = -1e30f; lsum[i] = 0.f;
        #pragma unroll
        for (int j = 0; j < 8; j++) o[i][j] = 0.f;
    }

    for (int kt = 0; kt <= qt; kt++) {
        __syncthreads();   // protect Kt/Vs/Ps from previous iteration
        for (int i = tid; i < 64 * 16; i += 128) {
            int r = i >> 4;
            int d4 = (i & 15) * 4;
            const float* krow = base + CDIM + (size_t)(kt * 64 + r) * C3;
            float4 kv = *(const float4*)(krow + d4);
            Kt[(d4 + 0) * 65 + r] = kv.x;
            Kt[(d4 + 1) * 65 + r] = kv.y;
            Kt[(d4 + 2) * 65 + r] = kv.z;
            Kt[(d4 + 3) * 65 + r] = kv.w;
            float4 vv = *(const float4*)(krow + CDIM + d4);
            *(float4*)(Vs + r * 64 + d4) = vv;
        }
        __syncthreads();

        // S = Q @ K^T (64x64, 4x8 per thread)
        float s[4][8];
        #pragma unroll
        for (int i = 0; i < 4; i++)
            #pragma unroll
            for (int j = 0; j < 8; j++) s[i][j] = 0.f;

        #pragma unroll 8
        for (int k = 0; k < 64; k++) {
            float qa[4], kb[8];
            #pragma unroll
            for (int i = 0; i < 4; i++) qa[i] = Qt[k * 65 + ty * 4 + i];
            #pragma unroll
            for (int j = 0; j < 8; j++) kb[j] = Kt[k * 65 + tx * 8 + j];
            #pragma unroll
            for (int i = 0; i < 4; i++)
                #pragma unroll
                for (int j = 0; j < 8; j++)
                    s[i][j] = fmaf(qa[i], kb[j], s[i][j]);
        }

        if (kt == qt) {  // causal mask on diagonal tile
            #pragma unroll
            for (int i = 0; i < 4; i++)
                #pragma unroll
                for (int j = 0; j < 8; j++)
                    if (tx * 8 + j > ty * 4 + i) s[i][j] = -1e30f;
        }

        // online softmax + write P to smem
        #pragma unroll
        for (int i = 0; i < 4; i++) {
            float mt = s[i][0];
            #pragma unroll
            for (int j = 1; j < 8; j++) mt = fmaxf(mt, s[i][j]);
            mt = fmaxf(mt, __shfl_xor_sync(0xffffffffu, mt, 1));
            mt = fmaxf(mt, __shfl_xor_sync(0xffffffffu, mt, 2));
            mt = fmaxf(mt, __shfl_xor_sync(0xffffffffu, mt, 4));
            float mn = fmaxf(m[i], mt);
            float alpha = __expf(m[i] - mn);
            m[i] = mn;
            float rs = 0.f;
            #pragma unroll
            for (int j = 0; j < 8; j++) {
                float p = __expf(s[i][j] - mn);
                s[i][j] = p;
                rs += p;
            }
            rs += __shfl_xor_sync(0xffffffffu, rs, 1);
            rs += __shfl_xor_sync(0xffffffffu, rs, 2);
            rs += __shfl_xor_sync(0xffffffffu, rs, 4);
            lsum[i] = lsum[i] * alpha + rs;
            #pragma unroll
            for (int j = 0; j < 8; j++) o[i][j] *= alpha;
            #pragma unroll
            for (int j = 0; j < 8; j++)
                Ps[(ty * 4 + i) * 65 + tx * 8 + j] = s[i][j];
        }
        __syncthreads();

        // O += P @ V
        #pragma unroll 4
        for (int kk = 0; kk < 64; kk++) {
            float pa[4];
            #pragma unroll
            for (int i = 0; i < 4; i++) pa[i] = Ps[(ty * 4 + i) * 65 + kk];
            float4 v0 = *(const float4*)(Vs + kk * 64 + tx * 8);
            float4 v1 = *(const float4*)(Vs + kk * 64 + tx * 8 + 4);
            #pragma unroll
            for (int i = 0; i < 4; i++) {
                o[i][0] = fmaf(pa[i], v0.x, o[i][0]);
                o[i][1] = fmaf(pa[i], v0.y, o[i][1]);
                o[i][2] = fmaf(pa[i], v0.z, o[i][2]);
                o[i][3] = fmaf(pa[i], v0.w, o[i][3]);
                o[i][4] = fmaf(pa[i], v1.x, o[i][4]);
                o[i][5] = fmaf(pa[i], v1.y, o[i][5]);
                o[i][6] = fmaf(pa[i], v1.z, o[i][6]);
                o[i][7] = fmaf(pa[i], v1.w, o[i][7]);
            }
        }
    }

    // write out[(b,t), h*64 + d]
    #pragma unroll
    for (int i = 0; i < 4; i++) {
        float inv = 1.f / lsum[i];
        int r = qt * 64 + ty * 4 + i;
        float* orow = out + ((size_t)(b * TLEN + r)) * CDIM + h * HD + tx * 8;
        float4 w0 = make_float4(o[i][0] * inv, o[i][1] * inv, o[i][2] * inv, o[i][3] * inv);
        float4 w1 = make_float4(o[i][4] * inv, o[i][5] * inv, o[i][6] * inv, o[i][7] * inv);
        *(float4*)(orow)     = w0;
        *(float4*)(orow + 4) = w1;
    }
}

// ---------------- launch ----------------
extern "C" void kernel_launch(void* const* d_in, const int* in_sizes, int n_in,
                              void* d_out, int out_size) {
    (void)in_sizes; (void)n_in; (void)out_size;
    const int*   idx   = (const int*)d_in[0];
    const float* emb   = (const float*)d_in[1];
    const float* pos   = (const float*)d_in[2];
    const float* Wqkv  = (const float*)d_in[3];
    const float* Wproj = (const float*)d_in[4];
    const float* ln1w  = (const float*)d_in[5];
    const float* ln1b  = (const float*)d_in[6];
    const float* ln2w  = (const float*)d_in[7];
    const float* ln2b  = (const float*)d_in[8];
    const float* W1    = (const float*)d_in[9];
    const float* b1    = (const float*)d_in[10];
    const float* W2    = (const float*)d_in[11];
    const float* b2    = (const float*)d_in[12];
    const float* lnfw  = (const float*)d_in[13];
    const float* lnfb  = (const float*)d_in[14];
    float* out = (float*)d_out;

    float *x, *xn, *att, *qkv, *hbuf, *embT;
    cudaGetSymbolAddress((void**)&x,    g_x);
    cudaGetSymbolAddress((void**)&xn,   g_xn);
    cudaGetSymbolAddress((void**)&att,  g_att);
    cudaGetSymbolAddress((void**)&qkv,  g_qkv);
    cudaGetSymbolAddress((void**)&hbuf, g_h);
    cudaGetSymbolAddress((void**)&embT, g_embT);

    cudaFuncSetAttribute(flash_kernel, cudaFuncAttributeMaxDynamicSharedMemorySize, FA_SM_BYTES);

    transpose_kernel<<<dim3(VPAD / 32, CDIM / 32), dim3(32, 8)>>>(emb);
    embed_kernel<<<MROWS, 256>>>(idx, emb, pos);

    const dim3 blk(256);
    for (int l = 0; l < LNUM; l++) {
        ln_kernel<<<MROWS, blk>>>(x, ln1w + l * CDIM, ln1b + l * CDIM, xn);

        gemm_kernel<0><<<dim3(3 * CDIM / GBN, MROWS / GBM), blk>>>(
            xn, Wqkv + (size_t)l * CDIM * 3 * CDIM, qkv,
            nullptr, nullptr, 3 * CDIM, CDIM, 3 * CDIM, 3 * CDIM);

        flash_kernel<<<dim3(TLEN / 64, HNUM, BSZ), 128, FA_SM_BYTES>>>(qkv, att);

        gemm_kernel<2><<<dim3(CDIM / GBN, MROWS / GBM), blk>>>(
            att, Wproj + (size_t)l * CDIM * CDIM, x,
            nullptr, x, CDIM, CDIM, CDIM, CDIM);

        ln_kernel<<<MROWS, blk>>>(x, ln2w + l * CDIM, ln2b + l * CDIM, xn);

        gemm_kernel<1><<<dim3(4 * CDIM / GBN, MROWS / GBM), blk>>>(
            xn, W1 + (size_t)l * CDIM * 4 * CDIM, hbuf,
            b1 + (size_t)l * 4 * CDIM, nullptr, 4 * CDIM, CDIM, 4 * CDIM, 4 * CDIM);

        gemm_kernel<3><<<dim3(CDIM / GBN, MROWS / GBM), blk>>>(
            hbuf, W2 + (size_t)l * 4 * CDIM * CDIM, x,
            b2 + (size_t)l * CDIM, x, CDIM, 4 * CDIM, CDIM, CDIM);
    }

    ln_kernel<<<MROWS, blk>>>(x, lnfw, lnfb, xn);

    // tied head: xn [2048,768] @ embT [768, VPAD] -> out [2048, 50257]
    gemm_kernel<0><<<dim3(VPAD / GBN, MROWS / GBM), blk>>>(
        xn, embT, out, nullptr, nullptr, VDIM, CDIM, VPAD, VDIM);
}

// round 15
// speedup vs baseline: 1.0023x; 1.0017x over previous
#include <cuda_runtime.h>
#include <math.h>

// ---------------- problem constants ----------------
#define CDIM 768
#define LNUM 6
#define HNUM 12
#define HD   64
#define TLEN 1024
#define BSZ  2
#define VDIM 50257
#define VPAD 50304               // 393 * 128, zero-padded
#define MROWS (BSZ * TLEN)       // 2048

// ---------------- scratch (no allocation allowed) ----------------
__device__ __align__(16) float g_x   [MROWS * CDIM];
__device__ __align__(16) float g_xn  [MROWS * CDIM];
__device__ __align__(16) float g_att [MROWS * CDIM];
__device__ __align__(16) float g_qkv [MROWS * 3 * CDIM];
__device__ __align__(16) float g_h   [MROWS * 4 * CDIM];
__device__ __align__(16) float g_embT[CDIM * VPAD];

// ---------------- embedding ----------------
__global__ void embed_kernel(const int* __restrict__ idx,
                             const float* __restrict__ emb,
                             const float* __restrict__ pos) {
    int n = blockIdx.x;
    int tok = idx[n];
    int t = n & (TLEN - 1);
    const float* e = emb + (size_t)tok * CDIM;
    const float* p = pos + (size_t)t * CDIM;
    float* xr = g_x + (size_t)n * CDIM;
    for (int c = threadIdx.x; c < CDIM; c += blockDim.x)
        xr[c] = e[c] + p[c];
}

// ---------------- transpose emb [V,C] -> embT [C, VPAD] (zero padded) ----------------
__global__ void transpose_kernel(const float* __restrict__ emb) {
    __shared__ float tile[32][33];
    int v0 = blockIdx.x * 32;
    int c0 = blockIdx.y * 32;
    for (int i = threadIdx.y; i < 32; i += 8) {
        int v = v0 + i;
        tile[i][threadIdx.x] = (v < VDIM) ? emb[(size_t)v * CDIM + c0 + threadIdx.x] : 0.f;
    }
    __syncthreads();
    for (int i = threadIdx.y; i < 32; i += 8) {
        g_embT[(size_t)(c0 + i) * VPAD + v0 + threadIdx.x] = tile[threadIdx.x][i];
    }
}

// ---------------- layernorm (one block per row, C=768) ----------------
__global__ void __launch_bounds__(256) ln_kernel(const float* __restrict__ x,
                                                 const float* __restrict__ w,
                                                 const float* __restrict__ bb,
                                                 float* __restrict__ y) {
    __shared__ float red[8];
    __shared__ float bc[2];
    int row = blockIdx.x, t = threadIdx.x;
    const float* xr = x + (size_t)row * CDIM;
    float v0 = xr[t], v1 = xr[t + 256], v2 = xr[t + 512];
    float s = v0 + v1 + v2;
    #pragma unroll
    for (int o = 16; o; o >>= 1) s += __shfl_xor_sync(0xffffffffu, s, o);
    if ((t & 31) == 0) red[t >> 5] = s;
    __syncthreads();
    if (t == 0) {
        float tt = 0.f;
        #pragma unroll
        for (int i = 0; i < 8; i++) tt += red[i];
        bc[0] = tt * (1.f / 768.f);
    }
    __syncthreads();
    float mu = bc[0];
    float d0 = v0 - mu, d1 = v1 - mu, d2 = v2 - mu;
    float q = d0 * d0 + d1 * d1 + d2 * d2;
    __syncthreads();   // red reuse
    #pragma unroll
    for (int o = 16; o; o >>= 1) q += __shfl_xor_sync(0xffffffffu, q, o);
    if ((t & 31) == 0) red[t >> 5] = q;
    __syncthreads();
    if (t == 0) {
        float tt = 0.f;
        #pragma unroll
        for (int i = 0; i < 8; i++) tt += red[i];
        bc[1] = rsqrtf(tt * (1.f / 768.f) + 1e-5f);
    }
    __syncthreads();
    float inv = bc[1];
    float* yr = y + (size_t)row * CDIM;
    yr[t]       = d0 * inv * w[t]       + bb[t];
    yr[t + 256] = d1 * inv * w[t + 256] + bb[t + 256];
    yr[t + 512] = d2 * inv * w[t + 512] + bb[t + 512];
}

// ---------------- SGEMM: C[M,N] = A[M,K] @ B[K,N]  (lda = K) ----------------
// EPI: 0 = none, 1 = +bias then GELU, 2 = +resid, 3 = +bias +resid
#define GBM 128
#define GBN 128
#define GBK 16

template<int EPI>
__global__ void __launch_bounds__(256) gemm_kernel(
    const float* __restrict__ A, const float* __restrict__ B, float* __restrict__ Cc,
    const float* __restrict__ bias, const float* __restrict__ resid,
    int N, int K, int ldb, int ldc)
{
    __shared__ float As[GBK][132];   // K-transposed A tile, padded stride
    __shared__ float Bs[GBK][GBN];

    int tid = threadIdx.x;
    int bn = blockIdx.x * GBN;
    int bm = blockIdx.y * GBM;
    int tx = tid & 15, ty = tid >> 4;

    int arow = tid >> 2;             // 0..63
    int acol = (tid & 3) << 2;       // 0,4,8,12
    int brow = tid >> 5;             // 0..7
    int bcol = (tid & 31) << 2;      // 0..124

    const float* Ap = A + (size_t)(bm + arow) * K + acol;
    const float* Bp = B + (size_t)brow * ldb + bn + bcol;

    float4 ra0 = *(const float4*)Ap;
    float4 ra1 = *(const float4*)(Ap + (size_t)64 * K);
    float4 rb0 = *(const float4*)Bp;
    float4 rb1 = *(const float4*)(Bp + (size_t)8 * ldb);

    float acc[8][8];
    #pragma unroll
    for (int i = 0; i < 8; i++)
        #pragma unroll
        for (int j = 0; j < 8; j++) acc[i][j] = 0.f;

    int nk = K / GBK;
    for (int kt = 0; kt < nk; kt++) {
        As[acol + 0][arow] = ra0.x; As[acol + 1][arow] = ra0.y;
        As[acol + 2][arow] = ra0.z; As[acol + 3][arow] = ra0.w;
        As[acol + 0][arow + 64] = ra1.x; As[acol + 1][arow + 64] = ra1.y;
        As[acol + 2][arow + 64] = ra1.z; As[acol + 3][arow + 64] = ra1.w;
        *(float4*)&Bs[brow][bcol]     = rb0;
        *(float4*)&Bs[brow + 8][bcol] = rb1;
        __syncthreads();

        if (kt + 1 < nk) {
            ra0 = *(const float4*)(Ap + (kt + 1) * GBK);
            ra1 = *(const float4*)(Ap + (size_t)64 * K + (kt + 1) * GBK);
            rb0 = *(const float4*)(Bp + (size_t)(kt + 1) * GBK * ldb);
            rb1 = *(const float4*)(Bp + (size_t)((kt + 1) * GBK + 8) * ldb);
        }

        #pragma unroll
        for (int k = 0; k < GBK; k++) {
            float4 a0 = *(const float4*)&As[k][ty * 8];
            float4 a1 = *(const float4*)&As[k][ty * 8 + 4];
            float4 b0 = *(const float4*)&Bs[k][tx * 8];
            float4 b1 = *(const float4*)&Bs[k][tx * 8 + 4];
            float av[8] = {a0.x, a0.y, a0.z, a0.w, a1.x, a1.y, a1.z, a1.w};
            float bv[8] = {b0.x, b0.y, b0.z, b0.w, b1.x, b1.y, b1.z, b1.w};
            #pragma unroll
            for (int i = 0; i < 8; i++)
                #pragma unroll
                for (int j = 0; j < 8; j++)
                    acc[i][j] = fmaf(av[i], bv[j], acc[i][j]);
        }
        __syncthreads();
    }

    float bvv[8];
    if (EPI == 1 || EPI == 3) {
        #pragma unroll
        for (int j = 0; j < 8; j++) {
            int n = bn + tx * 8 + j;
            bvv[j] = (n < N) ? bias[n] : 0.f;
        }
    }
    #pragma unroll
    for (int i = 0; i < 8; i++) {
        int mrow = bm + ty * 8 + i;
        float* crow = Cc + (size_t)mrow * ldc;
        const float* rrow = (EPI == 2 || EPI == 3) ? (resid + (size_t)mrow * ldc) : nullptr;
        #pragma unroll
        for (int j = 0; j < 8; j++) {
            int n = bn + tx * 8 + j;
            if (n >= N) continue;
            float v = acc[i][j];
            if (EPI == 1 || EPI == 3) v += bvv[j];
            if (EPI == 1) v = 0.5f * v * (1.f + erff(v * 0.70710678118654752f));
            if (EPI == 2 || EPI == 3) v += rrow[n];
            crow[n] = v;
        }
    }
}

// ---------------- fused causal flash attention ----------------
// Block = (q-tile of 64 rows, head h, batch b). 128 threads:
// ty = tid/8 in [0,16) -> 4 q-rows each; tx = tid%8 -> 8 cols each.
#define FA_SM_FLOATS (3 * 64 * 65 + 64 * 64)
#define FA_SM_BYTES  (FA_SM_FLOATS * 4)

__global__ void __launch_bounds__(128) flash_kernel(const float* __restrict__ qkv,
                                                    float* __restrict__ out) {
    extern __shared__ float sm[];
    float* Qt = sm;                  // [64 d][65] Q transposed, pre-scaled
    float* Kt = Qt + 64 * 65;        // [64 d][65] K transposed
    float* Ps = Kt + 64 * 65;        // [64 r][65] probabilities
    float* Vs = Ps + 64 * 65;        // [64 r][64 d]

    const int C3 = 3 * CDIM;
    int qt = blockIdx.x, h = blockIdx.y, b = blockIdx.z;
    int tid = threadIdx.x;
    int tx = tid & 7, ty = tid >> 3;

    const float* base = qkv + (size_t)b * TLEN * C3 + h * HD;

    // load Q tile (transposed, scaled by 1/sqrt(64))
    for (int i = tid; i < 64 * 16; i += 128) {
        int r = i >> 4;
        int d4 = (i & 15) * 4;
        float4 qv = *(const float4*)(base + (size_t)(qt * 64 + r) * C3 + d4);
        Qt[(d4 + 0) * 65 + r] = qv.x * 0.125f;
        Qt[(d4 + 1) * 65 + r] = qv.y * 0.125f;
        Qt[(d4 + 2) * 65 + r] = qv.z * 0.125f;
        Qt[(d4 + 3) * 65 + r] = qv.w * 0.125f;
    }

    float o[4][8];
    float m[4], lsum[4];
    #pragma unroll
    for (int i = 0; i < 4; i++) {
        m[i] = -1e30f; lsum[i] = 0.f;
        #pragma unroll
        for (int j = 0; j < 8; j++) o[i][j] = 0.f;
    }

    for (int kt = 0; kt <= qt; kt++) {
        __syncthreads();   // protect Kt/Vs/Ps from previous iteration
        for (int i = tid; i < 64 * 16; i += 128) {
            int r = i >> 4;
            int d4 = (i & 15) * 4;
            const float* krow = base + CDIM + (size_t)(kt * 64 + r) * C3;
            float4 kv = *(const float4*)(krow + d4);
            Kt[(d4 + 0) * 65 + r] = kv.x;
            Kt[(d4 + 1) * 65 + r] = kv.y;
            Kt[(d4 + 2) * 65 + r] = kv.z;
            Kt[(d4 + 3) * 65 + r] = kv.w;
            float4 vv = *(const float4*)(krow + CDIM + d4);
            *(float4*)(Vs + r * 64 + d4) = vv;
        }
        __syncthreads();

        // S = Q @ K^T (64x64, 4x8 per thread)
        float s[4][8];
        #pragma unroll
        for (int i = 0; i < 4; i++)
            #pragma unroll
            for (int j = 0; j < 8; j++) s[i][j] = 0.f;

        #pragma unroll 8
        for (int k = 0; k < 64; k++) {
            float qa[4], kb[8];
            #pragma unroll
            for (int i = 0; i < 4; i++) qa[i] = Qt[k * 65 + ty * 4 + i];
            #pragma unroll
            for (int j = 0; j < 8; j++) kb[j] = Kt[k * 65 + tx * 8 + j];
            #pragma unroll
            for (int i = 0; i < 4; i++)
                #pragma unroll
                for (int j = 0; j < 8; j++)
                    s[i][j] = fmaf(qa[i], kb[j], s[i][j]);
        }

        if (kt == qt) {  // causal mask on diagonal tile
            #pragma unroll
            for (int i = 0; i < 4; i++)
                #pragma unroll
                for (int j = 0; j < 8; j++)
                    if (tx * 8 + j > ty * 4 + i) s[i][j] = -1e30f;
        }

        // online softmax + write P to smem
        #pragma unroll
        for (int i = 0; i < 4; i++) {
            float mt = s[i][0];
            #pragma unroll
            for (int j = 1; j < 8; j++) mt = fmaxf(mt, s[i][j]);
            mt = fmaxf(mt, __shfl_xor_sync(0xffffffffu, mt, 1));
            mt = fmaxf(mt, __shfl_xor_sync(0xffffffffu, mt, 2));
            mt = fmaxf(mt, __shfl_xor_sync(0xffffffffu, mt, 4));
            float mn = fmaxf(m[i], mt);
            float alpha = __expf(m[i] - mn);
            m[i] = mn;
            float rs = 0.f;
            #pragma unroll
            for (int j = 0; j < 8; j++) {
                float p = __expf(s[i][j] - mn);
                s[i][j] = p;
                rs += p;
            }
            rs += __shfl_xor_sync(0xffffffffu, rs, 1);
            rs += __shfl_xor_sync(0xffffffffu, rs, 2);
            rs += __shfl_xor_sync(0xffffffffu, rs, 4);
            lsum[i] = lsum[i] * alpha + rs;
            #pragma unroll
            for (int j = 0; j < 8; j++) o[i][j] *= alpha;
            #pragma unroll
            for (int j = 0; j < 8; j++)
                Ps[(ty * 4 + i) * 65 + tx * 8 + j] = s[i][j];
        }
        __syncthreads();

        // O += P @ V
        #pragma unroll 4
        for (int kk = 0; kk < 64; kk++) {
            float pa[4];
            #pragma unroll
            for (int i = 0; i < 4; i++) pa[i] = Ps[(ty * 4 + i) * 65 + kk];
            float4 v0 = *(const float4*)(Vs + kk * 64 + tx * 8);
            float4 v1 = *(const float4*)(Vs + kk * 64 + tx * 8 + 4);
            #pragma unroll
            for (int i = 0; i < 4; i++) {
                o[i][0] = fmaf(pa[i], v0.x, o[i][0]);
                o[i][1] = fmaf(pa[i], v0.y, o[i][1]);
                o[i][2] = fmaf(pa[i], v0.z, o[i][2]);
                o[i][3] = fmaf(pa[i], v0.w, o[i][3]);
                o[i][4] = fmaf(pa[i], v1.x, o[i][4]);
                o[i][5] = fmaf(pa[i], v1.y, o[i][5]);
                o[i][6] = fmaf(pa[i], v1.z, o[i][6]);
                o[i][7] = fmaf(pa[i], v1.w, o[i][7]);
            }
        }
    }

    // write out[(b,t), h*64 + d]
    #pragma unroll
    for (int i = 0; i < 4; i++) {
        float inv = 1.f / lsum[i];
        int r = qt * 64 + ty * 4 + i;
        float* orow = out + ((size_t)(b * TLEN + r)) * CDIM + h * HD + tx * 8;
        float4 w0 = make_float4(o[i][0] * inv, o[i][1] * inv, o[i][2] * inv, o[i][3] * inv);
        float4 w1 = make_float4(o[i][4] * inv, o[i][5] * inv, o[i][6] * inv, o[i][7] * inv);
        *(float4*)(orow)     = w0;
        *(float4*)(orow + 4) = w1;
    }
}

// ---------------- launch ----------------
extern "C" void kernel_launch(void* const* d_in, const int* in_sizes, int n_in,
                              void* d_out, int out_size) {
    (void)in_sizes; (void)n_in; (void)out_size;
    const int*   idx   = (const int*)d_in[0];
    const float* emb   = (const float*)d_in[1];
    const float* pos   = (const float*)d_in[2];
    const float* Wqkv  = (const float*)d_in[3];
    const float* Wproj = (const float*)d_in[4];
    const float* ln1w  = (const float*)d_in[5];
    const float* ln1b  = (const float*)d_in[6];
    const float* ln2w  = (const float*)d_in[7];
    const float* ln2b  = (const float*)d_in[8];
    const float* W1    = (const float*)d_in[9];
    const float* b1    = (const float*)d_in[10];
    const float* W2    = (const float*)d_in[11];
    const float* b2    = (const float*)d_in[12];
    const float* lnfw  = (const float*)d_in[13];
    const float* lnfb  = (const float*)d_in[14];
    float* out = (float*)d_out;

    float *x, *xn, *att, *qkv, *hbuf, *embT;
    cudaGetSymbolAddress((void**)&x,    g_x);
    cudaGetSymbolAddress((void**)&xn,   g_xn);
    cudaGetSymbolAddress((void**)&att,  g_att);
    cudaGetSymbolAddress((void**)&qkv,  g_qkv);
    cudaGetSymbolAddress((void**)&hbuf, g_h);
    cudaGetSymbolAddress((void**)&embT, g_embT);

    cudaFuncSetAttribute(flash_kernel, cudaFuncAttributeMaxDynamicSharedMemorySize, FA_SM_BYTES);

    transpose_kernel<<<dim3(VPAD / 32, CDIM / 32), dim3(32, 8)>>>(emb);
    embed_kernel<<<MROWS, 256>>>(idx, emb, pos);

    const dim3 blk(256);
    for (int l = 0; l < LNUM; l++) {
        ln_kernel<<<MROWS, blk>>>(x, ln1w + l * CDIM, ln1b + l * CDIM, xn);

        gemm_kernel<0><<<dim3(3 * CDIM / GBN, MROWS / GBM), blk>>>(
            xn, Wqkv + (size_t)l * CDIM * 3 * CDIM, qkv,
            nullptr, nullptr, 3 * CDIM, CDIM, 3 * CDIM, 3 * CDIM);

        flash_kernel<<<dim3(TLEN / 64, HNUM, BSZ), 128, FA_SM_BYTES>>>(qkv, att);

        gemm_kernel<2><<<dim3(CDIM / GBN, MROWS / GBM), blk>>>(
            att, Wproj + (size_t)l * CDIM * CDIM, x,
            nullptr, x, CDIM, CDIM, CDIM, CDIM);

        ln_kernel<<<MROWS, blk>>>(x, ln2w + l * CDIM, ln2b + l * CDIM, xn);

        gemm_kernel<1><<<dim3(4 * CDIM / GBN, MROWS / GBM), blk>>>(
            xn, W1 + (size_t)l * CDIM * 4 * CDIM, hbuf,
            b1 + (size_t)l * 4 * CDIM, nullptr, 4 * CDIM, CDIM, 4 * CDIM, 4 * CDIM);

        gemm_kernel<3><<<dim3(CDIM / GBN, MROWS / GBM), blk>>>(
            hbuf, W2 + (size_t)l * 4 * CDIM * CDIM, x,
            b2 + (size_t)l * CDIM, x, CDIM, 4 * CDIM, CDIM, CDIM);
    }

    ln_kernel<<<MROWS, blk>>>(x, lnfw, lnfb, xn);

    // tied head: xn [2048,768] @ embT [768, VPAD] -> out [2048, 50257]
    gemm_kernel<0><<<dim3(VPAD / GBN, MROWS / GBM), blk>>>(
        xn, embT, out, nullptr, nullptr, VDIM, CDIM, VPAD, VDIM);
}

// round 17
// speedup vs baseline: 1.8384x; 1.8342x over previous
#include <cuda_runtime.h>
#include <cstdint>
#include <math.h>

// ---------------- problem constants ----------------
#define CDIM 768
#define LNUM 6
#define HNUM 12
#define HD   64
#define TLEN 1024
#define BSZ  2
#define VDIM 50257
#define VPAD 50304               // 393 * 128, zero-padded
#define MROWS (BSZ * TLEN)       // 2048

// ---------------- scratch (no allocation allowed) ----------------
__device__ __align__(16) float g_x   [MROWS * CDIM];
__device__ __align__(16) float g_xn  [MROWS * CDIM];
__device__ __align__(16) float g_att [MROWS * CDIM];
__device__ __align__(16) float g_qkv [MROWS * 3 * CDIM];
__device__ __align__(16) float g_h   [MROWS * 4 * CDIM];
__device__ __align__(16) float g_embT[CDIM * VPAD];

// ---------------- embedding ----------------
__global__ void embed_kernel(const int* __restrict__ idx,
                             const float* __restrict__ emb,
                             const float* __restrict__ pos) {
    int n = blockIdx.x;
    int tok = idx[n];
    int t = n & (TLEN - 1);
    const float* e = emb + (size_t)tok * CDIM;
    const float* p = pos + (size_t)t * CDIM;
    float* xr = g_x + (size_t)n * CDIM;
    for (int c = threadIdx.x; c < CDIM; c += blockDim.x)
        xr[c] = e[c] + p[c];
}

// ---------------- transpose emb [V,C] -> embT [C, VPAD] (zero padded) ----------------
__global__ void transpose_kernel(const float* __restrict__ emb) {
    __shared__ float tile[32][33];
    int v0 = blockIdx.x * 32;
    int c0 = blockIdx.y * 32;
    for (int i = threadIdx.y; i < 32; i += 8) {
        int v = v0 + i;
        tile[i][threadIdx.x] = (v < VDIM) ? emb[(size_t)v * CDIM + c0 + threadIdx.x] : 0.f;
    }
    __syncthreads();
    for (int i = threadIdx.y; i < 32; i += 8) {
        g_embT[(size_t)(c0 + i) * VPAD + v0 + threadIdx.x] = tile[threadIdx.x][i];
    }
}

// ---------------- layernorm (one block per row, C=768) ----------------
__global__ void __launch_bounds__(256) ln_kernel(const float* __restrict__ x,
                                                 const float* __restrict__ w,
                                                 const float* __restrict__ bb,
                                                 float* __restrict__ y) {
    __shared__ float red[8];
    __shared__ float bc[2];
    int row = blockIdx.x, t = threadIdx.x;
    const float* xr = x + (size_t)row * CDIM;
    float v0 = xr[t], v1 = xr[t + 256], v2 = xr[t + 512];
    float s = v0 + v1 + v2;
    #pragma unroll
    for (int o = 16; o; o >>= 1) s += __shfl_xor_sync(0xffffffffu, s, o);
    if ((t & 31) == 0) red[t >> 5] = s;
    __syncthreads();
    if (t == 0) {
        float tt = 0.f;
        #pragma unroll
        for (int i = 0; i < 8; i++) tt += red[i];
        bc[0] = tt * (1.f / 768.f);
    }
    __syncthreads();
    float mu = bc[0];
    float d0 = v0 - mu, d1 = v1 - mu, d2 = v2 - mu;
    float q = d0 * d0 + d1 * d1 + d2 * d2;
    __syncthreads();   // red reuse
    #pragma unroll
    for (int o = 16; o; o >>= 1) q += __shfl_xor_sync(0xffffffffu, q, o);
    if ((t & 31) == 0) red[t >> 5] = q;
    __syncthreads();
    if (t == 0) {
        float tt = 0.f;
        #pragma unroll
        for (int i = 0; i < 8; i++) tt += red[i];
        bc[1] = rsqrtf(tt * (1.f / 768.f) + 1e-5f);
    }
    __syncthreads();
    float inv = bc[1];
    float* yr = y + (size_t)row * CDIM;
    yr[t]       = d0 * inv * w[t]       + bb[t];
    yr[t + 256] = d1 * inv * w[t + 256] + bb[t + 256];
    yr[t + 512] = d2 * inv * w[t + 512] + bb[t + 512];
}

// ================= tensor-core split-bf16 GEMM =================
// C[M,N] = A[M,K] @ B[K,N], fp32 in/out. Accuracy: a = ah + al, b = bh + bl
// (bf16 RNE splits done with raw bit ops), accumulate ah*bh + ah*bl + al*bh
// in fp32 via mma.sync m16n8k16. Dropped al*bl term ~2^-18 relative.
// CTA tile 128x128x32, 8 warps of 64x32.
// EPI: 0 = none, 1 = +bias then GELU, 2 = +resid, 3 = +bias +resid

#define TB_M 128
#define TB_N 128
#define TB_K 32
#define ASTR 40     // bf16 elems per A smem row (80B: odd multiple of 16B)
#define BSTR 136    // bf16 elems per B smem row (272B: odd multiple of 16B)

__device__ __forceinline__ void ldsm_x4(unsigned& r0, unsigned& r1, unsigned& r2, unsigned& r3, unsigned addr) {
    asm volatile("ldmatrix.sync.aligned.m8n8.x4.shared.b16 {%0,%1,%2,%3}, [%4];"
                 : "=r"(r0), "=r"(r1), "=r"(r2), "=r"(r3) : "r"(addr));
}
__device__ __forceinline__ void ldsm_x4t(unsigned& r0, unsigned& r1, unsigned& r2, unsigned& r3, unsigned addr) {
    asm volatile("ldmatrix.sync.aligned.m8n8.x4.trans.shared.b16 {%0,%1,%2,%3}, [%4];"
                 : "=r"(r0), "=r"(r1), "=r"(r2), "=r"(r3) : "r"(addr));
}
__device__ __forceinline__ void mma_bf16(float* c,
                                         unsigned a0, unsigned a1, unsigned a2, unsigned a3,
                                         unsigned b0, unsigned b1) {
    asm volatile("mma.sync.aligned.m16n8k16.row.col.f32.bf16.bf16.f32 "
                 "{%0,%1,%2,%3}, {%4,%5,%6,%7}, {%8,%9}, {%0,%1,%2,%3};"
                 : "+f"(c[0]), "+f"(c[1]), "+f"(c[2]), "+f"(c[3])
                 : "r"(a0), "r"(a1), "r"(a2), "r"(a3), "r"(b0), "r"(b1));
}

// round-to-nearest-even fp32 -> bf16 (result in low 16 bits)
__device__ __forceinline__ unsigned f2bf(float f) {
    unsigned u = __float_as_uint(f);
    return (u + 0x7fffu + ((u >> 16) & 1u)) >> 16;
}

// split a float4 into hi/lo bf16 pairs, write 2 packed words each
__device__ __forceinline__ void split4(float4 v, unsigned* hp, unsigned* lp) {
    float f0 = v.x, f1 = v.y, f2 = v.z, f3 = v.w;
    unsigned h0 = f2bf(f0), h1 = f2bf(f1), h2 = f2bf(f2), h3 = f2bf(f3);
    unsigned l0 = f2bf(f0 - __uint_as_float(h0 << 16));
    unsigned l1 = f2bf(f1 - __uint_as_float(h1 << 16));
    unsigned l2 = f2bf(f2 - __uint_as_float(h2 << 16));
    unsigned l3 = f2bf(f3 - __uint_as_float(h3 << 16));
    hp[0] = h0 | (h1 << 16); hp[1] = h2 | (h3 << 16);
    lp[0] = l0 | (l1 << 16); lp[1] = l2 | (l3 << 16);
}

template<int EPI>
__global__ void __launch_bounds__(256) gemm_tc(
    const float* __restrict__ A, const float* __restrict__ B, float* __restrict__ Cc,
    const float* __restrict__ bias, const float* __restrict__ resid,
    int N, int K, int ldb, int ldc)
{
    // smem tiles stored as packed 2xbf16 words
    __shared__ unsigned Ah[TB_M * ASTR / 2];
    __shared__ unsigned Al[TB_M * ASTR / 2];
    __shared__ unsigned Bh[TB_K * BSTR / 2];
    __shared__ unsigned Bl[TB_K * BSTR / 2];

    int tid = threadIdx.x;
    int bn = blockIdx.x * TB_N, bm = blockIdx.y * TB_M;
    int lane = tid & 31, warp = tid >> 5;
    int wm = (warp >> 2) * 64;      // warp m-offset (0 or 64)
    int wn = (warp & 3) * 32;       // warp n-offset (0..96)

    // global pointers (each thread: 4 float4 for A, 4 float4 for B per k-tile)
    const float* Ap = A + (size_t)(bm + (tid >> 3)) * K + ((tid & 7) << 2);
    const float* Bp = B + (size_t)(tid >> 5) * ldb + bn + ((tid & 31) << 2);

    float4 pa[4], pb[4];
    #pragma unroll
    for (int i = 0; i < 4; i++) {
        pa[i] = *(const float4*)(Ap + (size_t)(32 * i) * K);
        pb[i] = *(const float4*)(Bp + (size_t)(8 * i) * ldb);
    }

    float acc[4][4][4];
    #pragma unroll
    for (int i = 0; i < 4; i++)
        #pragma unroll
        for (int j = 0; j < 4; j++)
            #pragma unroll
            for (int u = 0; u < 4; u++) acc[i][j][u] = 0.f;

    // ldmatrix base addresses (byte offsets; elem index * 2 bytes)
    int fr = lane & 15;             // fragment row select
    int fc = (lane >> 4) << 3;      // fragment col select (0/8)
    unsigned aBaseH = (unsigned)__cvta_generic_to_shared(Ah) + (unsigned)(((wm + fr) * ASTR + fc) * 2);
    unsigned aBaseL = (unsigned)__cvta_generic_to_shared(Al) + (unsigned)(((wm + fr) * ASTR + fc) * 2);
    unsigned bBaseH = (unsigned)__cvta_generic_to_shared(Bh) + (unsigned)((fr * BSTR + wn + fc) * 2);
    unsigned bBaseL = (unsigned)__cvta_generic_to_shared(Bl) + (unsigned)((fr * BSTR + wn + fc) * 2);

    int nk = K / TB_K;
    for (int kt = 0; kt < nk; kt++) {
        // stage tile to smem with hi/lo split
        #pragma unroll
        for (int i = 0; i < 4; i++) {
            int r = (tid >> 3) + 32 * i, c = (tid & 7) << 2;    // c multiple of 4 elems
            int w0 = (r * ASTR + c) >> 1;
            split4(pa[i], Ah + w0, Al + w0);
        }
        #pragma unroll
        for (int i = 0; i < 4; i++) {
            int r = (tid >> 5) + 8 * i, c = (tid & 31) << 2;
            int w0 = (r * BSTR + c) >> 1;
            split4(pb[i], Bh + w0, Bl + w0);
        }
        __syncthreads();

        if (kt + 1 < nk) {
            #pragma unroll
            for (int i = 0; i < 4; i++) {
                pa[i] = *(const float4*)(Ap + (kt + 1) * TB_K + (size_t)(32 * i) * K);
                pb[i] = *(const float4*)(Bp + (size_t)((kt + 1) * TB_K + 8 * i) * ldb);
            }
        }

        #pragma unroll
        for (int kk = 0; kk < 2; kk++) {            // two k16 substeps
            unsigned ah[4][4], al[4][4], bh[2][4], bl[2][4];
            #pragma unroll
            for (int i = 0; i < 4; i++) {
                unsigned off = (unsigned)((i * 16 * ASTR + kk * 16) * 2);
                ldsm_x4(ah[i][0], ah[i][1], ah[i][2], ah[i][3], aBaseH + off);
                ldsm_x4(al[i][0], al[i][1], al[i][2], al[i][3], aBaseL + off);
            }
            #pragma unroll
            for (int j = 0; j < 2; j++) {
                unsigned off = (unsigned)((kk * 16 * BSTR + j * 16) * 2);
                ldsm_x4t(bh[j][0], bh[j][1], bh[j][2], bh[j][3], bBaseH + off);
                ldsm_x4t(bl[j][0], bl[j][1], bl[j][2], bl[j][3], bBaseL + off);
            }
            #pragma unroll
            for (int i = 0; i < 4; i++) {
                #pragma unroll
                for (int j = 0; j < 2; j++) {
                    // hi x hi
                    mma_bf16(acc[i][2*j],   ah[i][0], ah[i][1], ah[i][2], ah[i][3], bh[j][0], bh[j][1]);
                    mma_bf16(acc[i][2*j+1], ah[i][0], ah[i][1], ah[i][2], ah[i][3], bh[j][2], bh[j][3]);
                    // hi x lo
                    mma_bf16(acc[i][2*j],   ah[i][0], ah[i][1], ah[i][2], ah[i][3], bl[j][0], bl[j][1]);
                    mma_bf16(acc[i][2*j+1], ah[i][0], ah[i][1], ah[i][2], ah[i][3], bl[j][2], bl[j][3]);
                    // lo x hi
                    mma_bf16(acc[i][2*j],   al[i][0], al[i][1], al[i][2], al[i][3], bh[j][0], bh[j][1]);
                    mma_bf16(acc[i][2*j+1], al[i][0], al[i][1], al[i][2], al[i][3], bh[j][2], bh[j][3]);
                }
            }
        }
        __syncthreads();
    }

    // ---------------- epilogue (C fragment: rows lane>>2 / +8, cols (lane&3)*2+u) ----------------
    #pragma unroll
    for (int i = 0; i < 4; i++) {
        int row = bm + wm + i * 16 + (lane >> 2);
        float* c0 = Cc + (size_t)row * ldc;
        float* c1 = Cc + (size_t)(row + 8) * ldc;
        #pragma unroll
        for (int jj = 0; jj < 4; jj++) {
            int col = bn + wn + jj * 8 + ((lane & 3) << 1);
            #pragma unroll
            for (int u = 0; u < 2; u++) {
                int n = col + u;
                if (n >= N) continue;
                float x0 = acc[i][jj][u];
                float x1 = acc[i][jj][2 + u];
                if (EPI == 1 || EPI == 3) { float bv = bias[n]; x0 += bv; x1 += bv; }
                if (EPI == 1) {
                    x0 = 0.5f * x0 * (1.f + erff(x0 * 0.70710678118654752f));
                    x1 = 0.5f * x1 * (1.f + erff(x1 * 0.70710678118654752f));
                }
                if (EPI == 2 || EPI == 3) {
                    x0 += resid[(size_t)row * ldc + n];
                    x1 += resid[(size_t)(row + 8) * ldc + n];
                }
                c0[n] = x0;
                c1[n] = x1;
            }
        }
    }
}

// ---------------- fused causal flash attention ----------------
// Block = (q-tile of 64 rows, head h, batch b). 128 threads:
// ty = tid/8 in [0,16) -> 4 q-rows each; tx = tid%8 -> 8 cols each.
#define FA_SM_FLOATS (3 * 64 * 65 + 64 * 64)
#define FA_SM_BYTES  (FA_SM_FLOATS * 4)

__global__ void __launch_bounds__(128) flash_kernel(const float* __restrict__ qkv,
                                                    float* __restrict__ out) {
    extern __shared__ float sm[];
    float* Qt = sm;                  // [64 d][65] Q transposed, pre-scaled
    float* Kt = Qt + 64 * 65;        // [64 d][65] K transposed
    float* Ps = Kt + 64 * 65;        // [64 r][65] probabilities
    float* Vs = Ps + 64 * 65;        // [64 r][64 d]

    const int C3 = 3 * CDIM;
    int qt = blockIdx.x, h = blockIdx.y, b = blockIdx.z;
    int tid = threadIdx.x;
    int tx = tid & 7, ty = tid >> 3;

    const float* base = qkv + (size_t)b * TLEN * C3 + h * HD;

    // load Q tile (transposed, scaled by 1/sqrt(64))
    for (int i = tid; i < 64 * 16; i += 128) {
        int r = i >> 4;
        int d4 = (i & 15) * 4;
        float4 qv = *(const float4*)(base + (size_t)(qt * 64 + r) * C3 + d4);
        Qt[(d4 + 0) * 65 + r] = qv.x * 0.125f;
        Qt[(d4 + 1) * 65 + r] = qv.y * 0.125f;
        Qt[(d4 + 2) * 65 + r] = qv.z * 0.125f;
        Qt[(d4 + 3) * 65 + r] = qv.w * 0.125f;
    }

    float o[4][8];
    float m[4], lsum[4];
    #pragma unroll
    for (int i = 0; i < 4; i++) {
        m[i] = -1e30f; lsum[i] = 0.f;
        #pragma unroll
        for (int j = 0; j < 8; j++) o[i][j] = 0.f;
    }

    for (int kt = 0; kt <= qt; kt++) {
        __syncthreads();   // protect Kt/Vs/Ps from previous iteration
        for (int i = tid; i < 64 * 16; i += 128) {
            int r = i >> 4;
            int d4 = (i & 15) * 4;
            const float* krow = base + CDIM + (size_t)(kt * 64 + r) * C3;
            float4 kv = *(const float4*)(krow + d4);
            Kt[(d4 + 0) * 65 + r] = kv.x;
            Kt[(d4 + 1) * 65 + r] = kv.y;
            Kt[(d4 + 2) * 65 + r] = kv.z;
            Kt[(d4 + 3) * 65 + r] = kv.w;
            float4 vv = *(const float4*)(krow + CDIM + d4);
            *(float4*)(Vs + r * 64 + d4) = vv;
        }
        __syncthreads();

        // S = Q @ K^T (64x64, 4x8 per thread)
        float s[4][8];
        #pragma unroll
        for (int i = 0; i < 4; i++)
            #pragma unroll
            for (int j = 0; j < 8; j++) s[i][j] = 0.f;

        #pragma unroll 8
        for (int k = 0; k < 64; k++) {
            float qa[4], kb[8];
            #pragma unroll
            for (int i = 0; i < 4; i++) qa[i] = Qt[k * 65 + ty * 4 + i];
            #pragma unroll
            for (int j = 0; j < 8; j++) kb[j] = Kt[k * 65 + tx * 8 + j];
            #pragma unroll
            for (int i = 0; i < 4; i++)
                #pragma unroll
                for (int j = 0; j < 8; j++)
                    s[i][j] = fmaf(qa[i], kb[j], s[i][j]);
        }

        if (kt == qt) {  // causal mask on diagonal tile
            #pragma unroll
            for (int i = 0; i < 4; i++)
                #pragma unroll
                for (int j = 0; j < 8; j++)
                    if (tx * 8 + j > ty * 4 + i) s[i][j] = -1e30f;
        }

        // online softmax + write P to smem
        #pragma unroll
        for (int i = 0; i < 4; i++) {
            float mt = s[i][0];
            #pragma unroll
            for (int j = 1; j < 8; j++) mt = fmaxf(mt, s[i][j]);
            mt = fmaxf(mt, __shfl_xor_sync(0xffffffffu, mt, 1));
            mt = fmaxf(mt, __shfl_xor_sync(0xffffffffu, mt, 2));
            mt = fmaxf(mt, __shfl_xor_sync(0xffffffffu, mt, 4));
            float mn = fmaxf(m[i], mt);
            float alpha = __expf(m[i] - mn);
            m[i] = mn;
            float rs = 0.f;
            #pragma unroll
            for (int j = 0; j < 8; j++) {
                float p = __expf(s[i][j] - mn);
                s[i][j] = p;
                rs += p;
            }
            rs += __shfl_xor_sync(0xffffffffu, rs, 1);
            rs += __shfl_xor_sync(0xffffffffu, rs, 2);
            rs += __shfl_xor_sync(0xffffffffu, rs, 4);
            lsum[i] = lsum[i] * alpha + rs;
            #pragma unroll
            for (int j = 0; j < 8; j++) o[i][j] *= alpha;
            #pragma unroll
            for (int j = 0; j < 8; j++)
                Ps[(ty * 4 + i) * 65 + tx * 8 + j] = s[i][j];
        }
        __syncthreads();

        // O += P @ V
        #pragma unroll 4
        for (int kk = 0; kk < 64; kk++) {
            float pa[4];
            #pragma unroll
            for (int i = 0; i < 4; i++) pa[i] = Ps[(ty * 4 + i) * 65 + kk];
            float4 v0 = *(const float4*)(Vs + kk * 64 + tx * 8);
            float4 v1 = *(const float4*)(Vs + kk * 64 + tx * 8 + 4);
            #pragma unroll
            for (int i = 0; i < 4; i++) {
                o[i][0] = fmaf(pa[i], v0.x, o[i][0]);
                o[i][1] = fmaf(pa[i], v0.y, o[i][1]);
                o[i][2] = fmaf(pa[i], v0.z, o[i][2]);
                o[i][3] = fmaf(pa[i], v0.w, o[i][3]);
                o[i][4] = fmaf(pa[i], v1.x, o[i][4]);
                o[i][5] = fmaf(pa[i], v1.y, o[i][5]);
                o[i][6] = fmaf(pa[i], v1.z, o[i][6]);
                o[i][7] = fmaf(pa[i], v1.w, o[i][7]);
            }
        }
    }

    // write out[(b,t), h*64 + d]
    #pragma unroll
    for (int i = 0; i < 4; i++) {
        float inv = 1.f / lsum[i];
        int r = qt * 64 + ty * 4 + i;
        float* orow = out + ((size_t)(b * TLEN + r)) * CDIM + h * HD + tx * 8;
        float4 w0 = make_float4(o[i][0] * inv, o[i][1] * inv, o[i][2] * inv, o[i][3] * inv);
        float4 w1 = make_float4(o[i][4] * inv, o[i][5] * inv, o[i][6] * inv, o[i][7] * inv);
        *(float4*)(orow)     = w0;
        *(float4*)(orow + 4) = w1;
    }
}

// ---------------- launch ----------------
extern "C" void kernel_launch(void* const* d_in, const int* in_sizes, int n_in,
                              void* d_out, int out_size) {
    (void)in_sizes; (void)n_in; (void)out_size;
    const int*   idx   = (const int*)d_in[0];
    const float* emb   = (const float*)d_in[1];
    const float* pos   = (const float*)d_in[2];
    const float* Wqkv  = (const float*)d_in[3];
    const float* Wproj = (const float*)d_in[4];
    const float* ln1w  = (const float*)d_in[5];
    const float* ln1b  = (const float*)d_in[6];
    const float* ln2w  = (const float*)d_in[7];
    const float* ln2b  = (const float*)d_in[8];
    const float* W1    = (const float*)d_in[9];
    const float* b1    = (const float*)d_in[10];
    const float* W2    = (const float*)d_in[11];
    const float* b2    = (const float*)d_in[12];
    const float* lnfw  = (const float*)d_in[13];
    const float* lnfb  = (const float*)d_in[14];
    float* out = (float*)d_out;

    float *x, *xn, *att, *qkv, *hbuf, *embT;
    cudaGetSymbolAddress((void**)&x,    g_x);
    cudaGetSymbolAddress((void**)&xn,   g_xn);
    cudaGetSymbolAddress((void**)&att,  g_att);
    cudaGetSymbolAddress((void**)&qkv,  g_qkv);
    cudaGetSymbolAddress((void**)&hbuf, g_h);
    cudaGetSymbolAddress((void**)&embT, g_embT);

    cudaFuncSetAttribute(flash_kernel, cudaFuncAttributeMaxDynamicSharedMemorySize, FA_SM_BYTES);

    transpose_kernel<<<dim3(VPAD / 32, CDIM / 32), dim3(32, 8)>>>(emb);
    embed_kernel<<<MROWS, 256>>>(idx, emb, pos);

    const dim3 blk(256);
    for (int l = 0; l < LNUM; l++) {
        ln_kernel<<<MROWS, blk>>>(x, ln1w + l * CDIM, ln1b + l * CDIM, xn);

        gemm_tc<0><<<dim3(3 * CDIM / TB_N, MROWS / TB_M), blk>>>(
            xn, Wqkv + (size_t)l * CDIM * 3 * CDIM, qkv,
            nullptr, nullptr, 3 * CDIM, CDIM, 3 * CDIM, 3 * CDIM);

        flash_kernel<<<dim3(TLEN / 64, HNUM, BSZ), 128, FA_SM_BYTES>>>(qkv, att);

        gemm_tc<2><<<dim3(CDIM / TB_N, MROWS / TB_M), blk>>>(
            att, Wproj + (size_t)l * CDIM * CDIM, x,
            nullptr, x, CDIM, CDIM, CDIM, CDIM);

        ln_kernel<<<MROWS, blk>>>(x, ln2w + l * CDIM, ln2b + l * CDIM, xn);

        gemm_tc<1><<<dim3(4 * CDIM / TB_N, MROWS / TB_M), blk>>>(
            xn, W1 + (size_t)l * CDIM * 4 * CDIM, hbuf,
            b1 + (size_t)l * 4 * CDIM, nullptr, 4 * CDIM, CDIM, 4 * CDIM, 4 * CDIM);

        gemm_tc<3><<<dim3(CDIM / TB_N, MROWS / TB_M), blk>>>(
            hbuf, W2 + (size_t)l * 4 * CDIM * CDIM, x,
            b2 + (size_t)l * CDIM, x, CDIM, 4 * CDIM, CDIM, CDIM);
    }

    ln_kernel<<<MROWS, blk>>>(x, lnfw, lnfb, xn);

    // tied head: xn [2048,768] @ embT [768, VPAD] -> out [2048, 50257]
    gemm_tc<0><<<dim3(VPAD / TB_N, MROWS / TB_M), blk>>>(
        xn, embT, out, nullptr, nullptr, VDIM, CDIM, VPAD, VDIM);
}